// round 1
// baseline (speedup 1.0000x reference)
#include <cuda_runtime.h>
#include <math.h>

#define SEQ   2048
#define HID   1024
#define NTOK  1024
#define NHEAD 16
#define HDIM  64

// Scratch (device globals — no allocation allowed in kernel_launch)
__device__ float g_attn[SEQ * NTOK];
__device__ float g_q[SEQ * HID];
__device__ float g_k[SEQ * HID];
__device__ float g_v[SEQ * HID];
__device__ float g_ctx[SEQ * HID];

// ---------------------------------------------------------------------------
// SGEMM: C[M,N] = A[M,K] * op(B)
//   BT = true : B is [N,K] row-major (C = A * B^T)
//   BT = false: B is [K,N] row-major (C = A * B)
// 128x128 tile, BK=8, 256 threads, 8x8 per thread. M,N,K multiples of 128/8.
// ---------------------------------------------------------------------------
template <bool BT>
__global__ void __launch_bounds__(256) sgemm128(const float* __restrict__ A,
                                                const float* __restrict__ B,
                                                float* __restrict__ C,
                                                int M, int N, int K)
{
    __shared__ float As[8][128];
    __shared__ float Bs[8][128];

    const int tid = threadIdx.x;
    const int bx = blockIdx.x;   // N tile
    const int by = blockIdx.y;   // M tile
    const int tx = tid & 15;
    const int ty = tid >> 4;

    // Global load pointers
    const float* Aptr = A + (size_t)(by * 128 + (tid >> 1)) * K + (tid & 1) * 4;
    const float* Bptr;
    if (BT) {
        Bptr = B + (size_t)(bx * 128 + (tid >> 1)) * K + (tid & 1) * 4;
    } else {
        Bptr = B + (size_t)(tid >> 5) * N + bx * 128 + (tid & 31) * 4;
    }

    float c[8][8];
#pragma unroll
    for (int i = 0; i < 8; i++)
#pragma unroll
        for (int j = 0; j < 8; j++) c[i][j] = 0.f;

    const int arow = tid >> 1;
    const int acol = (tid & 1) * 4;

    for (int kt = 0; kt < K; kt += 8) {
        float4 av = *(const float4*)(Aptr + kt);
        float4 bv;
        if (BT) bv = *(const float4*)(Bptr + kt);
        else    bv = *(const float4*)(Bptr + (size_t)kt * N);

        __syncthreads();  // previous tile compute done before overwriting smem

        // A: transpose into As[k][m]
        As[acol + 0][arow] = av.x;
        As[acol + 1][arow] = av.y;
        As[acol + 2][arow] = av.z;
        As[acol + 3][arow] = av.w;

        if (BT) {
            // B[N,K]: transpose into Bs[k][n]
            Bs[acol + 0][arow] = bv.x;
            Bs[acol + 1][arow] = bv.y;
            Bs[acol + 2][arow] = bv.z;
            Bs[acol + 3][arow] = bv.w;
        } else {
            // B[K,N]: direct
            *(float4*)&Bs[tid >> 5][(tid & 31) * 4] = bv;
        }
        __syncthreads();

#pragma unroll
        for (int kk = 0; kk < 8; kk++) {
            float a[8], b[8];
#pragma unroll
            for (int i = 0; i < 8; i++) {
                a[i] = As[kk][ty * 8 + i];
                b[i] = Bs[kk][tx * 8 + i];
            }
#pragma unroll
            for (int i = 0; i < 8; i++)
#pragma unroll
                for (int j = 0; j < 8; j++) c[i][j] += a[i] * b[j];
        }
    }

#pragma unroll
    for (int i = 0; i < 8; i++) {
        float* Cp = C + (size_t)(by * 128 + ty * 8 + i) * N + bx * 128 + tx * 8;
        *(float4*)(Cp)     = make_float4(c[i][0], c[i][1], c[i][2], c[i][3]);
        *(float4*)(Cp + 4) = make_float4(c[i][4], c[i][5], c[i][6], c[i][7]);
    }
}

// ---------------------------------------------------------------------------
// Row-wise exact-gelu + L2 normalize * sqrt(NTOK), in place. One block per row.
// ---------------------------------------------------------------------------
__global__ void __launch_bounds__(256) gelu_l2norm(float* __restrict__ buf)
{
    const int row = blockIdx.x;
    const int tid = threadIdx.x;
    __shared__ float g[NTOK];
    __shared__ float ws[8];

    float* rp = buf + (size_t)row * NTOK;

    float ss = 0.f;
    for (int i = tid; i < NTOK; i += 256) {
        float v = rp[i];
        float gv = 0.5f * v * (1.f + erff(v * 0.70710678118654752f));
        g[i] = gv;
        ss += gv * gv;
    }
#pragma unroll
    for (int o = 16; o > 0; o >>= 1) ss += __shfl_xor_sync(0xffffffffu, ss, o);
    if ((tid & 31) == 0) ws[tid >> 5] = ss;
    __syncthreads();

    float tot = 0.f;
#pragma unroll
    for (int w = 0; w < 8; w++) tot += ws[w];

    const float sc = 32.f * rsqrtf(tot);  // sqrt(1024) = 32
    for (int i = tid; i < NTOK; i += 256) rp[i] = g[i] * sc;
}

// ---------------------------------------------------------------------------
// Causal flash attention, fp32. scale = 1/sqrt(64) = 0.125.
// Grid: (SEQ/128, NHEAD), 128 threads, one q-row per thread.
// Q/K/V/O layout: [SEQ, HID] with head h at columns [h*64, h*64+64).
// ---------------------------------------------------------------------------
__global__ void __launch_bounds__(128) flash_causal(const float* __restrict__ Q,
                                                    const float* __restrict__ K,
                                                    const float* __restrict__ V,
                                                    float* __restrict__ O)
{
    __shared__ float Ks[32][HDIM];
    __shared__ float Vs[32][HDIM];
    __shared__ float Sc[128][33];   // padded: conflict-free per-thread scores

    const int tid  = threadIdx.x;
    const int head = blockIdx.y;
    const int qrow = blockIdx.x * 128 + tid;

    const float* qp = Q + (size_t)qrow * HID + head * HDIM;
    float q[HDIM], acc[HDIM];
#pragma unroll
    for (int d = 0; d < HDIM; d += 4) {
        float4 t = *(const float4*)(qp + d);
        q[d] = t.x; q[d + 1] = t.y; q[d + 2] = t.z; q[d + 3] = t.w;
    }
#pragma unroll
    for (int d = 0; d < HDIM; d++) acc[d] = 0.f;

    float m = -1e30f, l = 0.f;
    const int kend = blockIdx.x * 128 + 128;  // last kv needed by any thread here

    for (int kb = 0; kb < kend; kb += 32) {
        __syncthreads();
        // cooperative K/V tile load: 32 rows x 64 dims, float4
        for (int i = tid; i < 32 * 16; i += 128) {
            int j = i >> 4, d4 = (i & 15) << 2;
            *(float4*)&Ks[j][d4] =
                *(const float4*)(K + (size_t)(kb + j) * HID + head * HDIM + d4);
            *(float4*)&Vs[j][d4] =
                *(const float4*)(V + (size_t)(kb + j) * HID + head * HDIM + d4);
        }
        __syncthreads();

        float tmax = -1e30f;
        for (int j = 0; j < 32; j++) {
            float s = 0.f;
#pragma unroll
            for (int d = 0; d < HDIM; d++) s += q[d] * Ks[j][d];
            s *= 0.125f;
            if (kb + j > qrow) s = -1e30f;
            Sc[tid][j] = s;
            tmax = fmaxf(tmax, s);
        }

        if (tmax > -1e29f) {
            float mnew = fmaxf(m, tmax);
            float corr = __expf(m - mnew);
            l *= corr;
#pragma unroll
            for (int d = 0; d < HDIM; d++) acc[d] *= corr;
            for (int j = 0; j < 32; j++) {
                float p = __expf(Sc[tid][j] - mnew);
                l += p;
#pragma unroll
                for (int d = 0; d < HDIM; d++) acc[d] += p * Vs[j][d];
            }
            m = mnew;
        }
    }

    const float inv = 1.f / l;
    float* op = O + (size_t)qrow * HID + head * HDIM;
#pragma unroll
    for (int d = 0; d < HDIM; d += 4) {
        *(float4*)(op + d) = make_float4(acc[d] * inv, acc[d + 1] * inv,
                                         acc[d + 2] * inv, acc[d + 3] * inv);
    }
}

// ---------------------------------------------------------------------------
// Launch: x -> Q/K/V pattention -> causal attention -> proj pattention -> out
// ---------------------------------------------------------------------------
extern "C" void kernel_launch(void* const* d_in, const int* in_sizes, int n_in,
                              void* d_out, int out_size)
{
    const float* x  = (const float*)d_in[0];
    const float* qk = (const float*)d_in[1];
    const float* qv = (const float*)d_in[2];
    const float* kk = (const float*)d_in[3];
    const float* kv = (const float*)d_in[4];
    const float* vk = (const float*)d_in[5];
    const float* vv = (const float*)d_in[6];
    const float* pk = (const float*)d_in[7];
    const float* pv = (const float*)d_in[8];
    float* out = (float*)d_out;

    float *attn, *q, *k, *v, *ctx;
    cudaGetSymbolAddress((void**)&attn, g_attn);
    cudaGetSymbolAddress((void**)&q,    g_q);
    cudaGetSymbolAddress((void**)&k,    g_k);
    cudaGetSymbolAddress((void**)&v,    g_v);
    cudaGetSymbolAddress((void**)&ctx,  g_ctx);

    dim3 gg(HID / 128, SEQ / 128);   // (8, 16) — same for all GEMMs here

    // Q pattention
    sgemm128<true ><<<gg, 256>>>(x,    qk, attn, SEQ, NTOK, HID);
    gelu_l2norm    <<<SEQ, 256>>>(attn);
    sgemm128<false><<<gg, 256>>>(attn, qv, q,    SEQ, HID,  NTOK);
    // K pattention
    sgemm128<true ><<<gg, 256>>>(x,    kk, attn, SEQ, NTOK, HID);
    gelu_l2norm    <<<SEQ, 256>>>(attn);
    sgemm128<false><<<gg, 256>>>(attn, kv, k,    SEQ, HID,  NTOK);
    // V pattention
    sgemm128<true ><<<gg, 256>>>(x,    vk, attn, SEQ, NTOK, HID);
    gelu_l2norm    <<<SEQ, 256>>>(attn);
    sgemm128<false><<<gg, 256>>>(attn, vv, v,    SEQ, HID,  NTOK);

    // causal multi-head attention
    flash_causal<<<dim3(SEQ / 128, NHEAD), 128>>>(q, k, v, ctx);

    // output projection pattention -> d_out
    sgemm128<true ><<<gg, 256>>>(ctx,  pk, attn, SEQ, NTOK, HID);
    gelu_l2norm    <<<SEQ, 256>>>(attn);
    sgemm128<false><<<gg, 256>>>(attn, pv, out,  SEQ, HID,  NTOK);
}

// round 2
// speedup vs baseline: 1.0547x; 1.0547x over previous
#include <cuda_runtime.h>
#include <mma.h>
#include <math.h>

using namespace nvcuda;

#define SEQ   2048
#define HID   1024
#define NTOK  1024
#define NHEAD 16
#define HDIM  64

// Scratch (device globals — no allocation allowed in kernel_launch)
__device__ float g_attn[SEQ * NTOK];
__device__ float g_q[SEQ * HID];
__device__ float g_k[SEQ * HID];
__device__ float g_v[SEQ * HID];
__device__ float g_ctx[SEQ * HID];

__device__ __forceinline__ float tf32_rna(float x) {
    float r;
    asm("cvt.rna.tf32.f32 %0, %1;" : "=f"(r) : "f"(x));
    return r;
}

// ---------------------------------------------------------------------------
// Tensor-core GEMM (tf32x3 compensated, ~fp32 accuracy):
//   C[M,N] = A[M,K] * op(B)
//   BT = true : B is [N,K] row-major (C = A * B^T)
//   BT = false: B is [K,N] row-major (C = A * B)
// 128x128 block tile, BK=32, 256 threads (8 warps, 4x2), warp tile 32x64.
// All dims must be multiples of 128 (M,N) / 32 (K) — true for this problem.
// ---------------------------------------------------------------------------
template <bool BT>
__global__ void __launch_bounds__(256) tgemm128(const float* __restrict__ A,
                                                const float* __restrict__ B,
                                                float* __restrict__ C,
                                                int M, int N, int K)
{
    constexpr int LDA = 40;                       // 32 + 8 pad (mult of 8)
    constexpr int LDB = BT ? 40 : 136;            // [n][k] pad / [k][n] pad
    __shared__ float As[128 * LDA];
    __shared__ float Bs[BT ? (128 * 40) : (32 * 136)];

    const int tid = threadIdx.x;
    const int bx = blockIdx.x;   // N tile
    const int by = blockIdx.y;   // M tile
    const int wid = tid >> 5;
    const int wm = wid & 3;      // 0..3  (m)
    const int wn = wid >> 2;     // 0..1  (n)

    wmma::fragment<wmma::accumulator, 16, 16, 8, float> cf[2][4];
#pragma unroll
    for (int mi = 0; mi < 2; mi++)
#pragma unroll
        for (int ni = 0; ni < 4; ni++) wmma::fill_fragment(cf[mi][ni], 0.f);

    for (int kt = 0; kt < K; kt += 32) {
        // ---- stage A tile: 128 rows x 32 k ----
#pragma unroll
        for (int i = 0; i < 4; i++) {
            int idx = tid + i * 256;
            int row = idx >> 3;
            int kq  = (idx & 7) * 4;
            float4 v = *(const float4*)(A + (size_t)(by * 128 + row) * K + kt + kq);
            *(float4*)(As + row * LDA + kq) = v;
        }
        // ---- stage B tile ----
        if (BT) {
            // B[N,K] row-major -> Bs[n][k] (col-major k x n for wmma)
#pragma unroll
            for (int i = 0; i < 4; i++) {
                int idx = tid + i * 256;
                int row = idx >> 3;
                int kq  = (idx & 7) * 4;
                float4 v = *(const float4*)(B + (size_t)(bx * 128 + row) * K + kt + kq);
                *(float4*)(Bs + row * 40 + kq) = v;
            }
        } else {
            // B[K,N] row-major -> Bs[k][n] (row-major)
#pragma unroll
            for (int i = 0; i < 4; i++) {
                int idx = tid + i * 256;
                int kr = idx >> 5;
                int nq = (idx & 31) * 4;
                float4 v = *(const float4*)(B + (size_t)(kt + kr) * N + bx * 128 + nq);
                *(float4*)(Bs + kr * 136 + nq) = v;
            }
        }
        __syncthreads();

        // ---- compute: 4 k-atoms of 8 ----
#pragma unroll
        for (int kk = 0; kk < 4; kk++) {
            wmma::fragment<wmma::matrix_a, 16, 16, 8, wmma::precision::tf32,
                           wmma::row_major> ahi[2], alo[2];
#pragma unroll
            for (int mi = 0; mi < 2; mi++) {
                wmma::load_matrix_sync(ahi[mi],
                    As + (wm * 32 + mi * 16) * LDA + kk * 8, LDA);
#pragma unroll
                for (int e = 0; e < ahi[mi].num_elements; e++) {
                    float x = ahi[mi].x[e];
                    float h = tf32_rna(x);
                    ahi[mi].x[e] = h;
                    alo[mi].x[e] = tf32_rna(x - h);
                }
            }
            if (BT) {
                wmma::fragment<wmma::matrix_b, 16, 16, 8, wmma::precision::tf32,
                               wmma::col_major> bhi[4], blo[4];
#pragma unroll
                for (int ni = 0; ni < 4; ni++) {
                    wmma::load_matrix_sync(bhi[ni],
                        Bs + (wn * 64 + ni * 16) * 40 + kk * 8, 40);
#pragma unroll
                    for (int e = 0; e < bhi[ni].num_elements; e++) {
                        float x = bhi[ni].x[e];
                        float h = tf32_rna(x);
                        bhi[ni].x[e] = h;
                        blo[ni].x[e] = tf32_rna(x - h);
                    }
                }
#pragma unroll
                for (int mi = 0; mi < 2; mi++)
#pragma unroll
                    for (int ni = 0; ni < 4; ni++) {
                        wmma::mma_sync(cf[mi][ni], ahi[mi], bhi[ni], cf[mi][ni]);
                        wmma::mma_sync(cf[mi][ni], alo[mi], bhi[ni], cf[mi][ni]);
                        wmma::mma_sync(cf[mi][ni], ahi[mi], blo[ni], cf[mi][ni]);
                    }
            } else {
                wmma::fragment<wmma::matrix_b, 16, 16, 8, wmma::precision::tf32,
                               wmma::row_major> bhi[4], blo[4];
#pragma unroll
                for (int ni = 0; ni < 4; ni++) {
                    wmma::load_matrix_sync(bhi[ni],
                        Bs + (kk * 8) * 136 + wn * 64 + ni * 16, 136);
#pragma unroll
                    for (int e = 0; e < bhi[ni].num_elements; e++) {
                        float x = bhi[ni].x[e];
                        float h = tf32_rna(x);
                        bhi[ni].x[e] = h;
                        blo[ni].x[e] = tf32_rna(x - h);
                    }
                }
#pragma unroll
                for (int mi = 0; mi < 2; mi++)
#pragma unroll
                    for (int ni = 0; ni < 4; ni++) {
                        wmma::mma_sync(cf[mi][ni], ahi[mi], bhi[ni], cf[mi][ni]);
                        wmma::mma_sync(cf[mi][ni], alo[mi], bhi[ni], cf[mi][ni]);
                        wmma::mma_sync(cf[mi][ni], ahi[mi], blo[ni], cf[mi][ni]);
                    }
            }
        }
        __syncthreads();
    }

    // ---- epilogue ----
#pragma unroll
    for (int mi = 0; mi < 2; mi++)
#pragma unroll
        for (int ni = 0; ni < 4; ni++) {
            float* Cp = C + (size_t)(by * 128 + wm * 32 + mi * 16) * N
                          + bx * 128 + wn * 64 + ni * 16;
            wmma::store_matrix_sync(Cp, cf[mi][ni], N, wmma::mem_row_major);
        }
}

// ---------------------------------------------------------------------------
// Row-wise exact-gelu + L2 normalize * sqrt(NTOK), in place. One block per row.
// ---------------------------------------------------------------------------
__global__ void __launch_bounds__(256) gelu_l2norm(float* __restrict__ buf)
{
    const int row = blockIdx.x;
    const int tid = threadIdx.x;
    __shared__ float g[NTOK];
    __shared__ float ws[8];

    float* rp = buf + (size_t)row * NTOK;

    float ss = 0.f;
    for (int i = tid; i < NTOK; i += 256) {
        float v = rp[i];
        float gv = 0.5f * v * (1.f + erff(v * 0.70710678118654752f));
        g[i] = gv;
        ss += gv * gv;
    }
#pragma unroll
    for (int o = 16; o > 0; o >>= 1) ss += __shfl_xor_sync(0xffffffffu, ss, o);
    if ((tid & 31) == 0) ws[tid >> 5] = ss;
    __syncthreads();

    float tot = 0.f;
#pragma unroll
    for (int w = 0; w < 8; w++) tot += ws[w];

    const float sc = 32.f * rsqrtf(tot);  // sqrt(1024) = 32
    for (int i = tid; i < NTOK; i += 256) rp[i] = g[i] * sc;
}

// ---------------------------------------------------------------------------
// Causal flash attention, fp32. scale = 1/sqrt(64) = 0.125.
// Grid: (SEQ/128, NHEAD), 128 threads, one q-row per thread.
// ---------------------------------------------------------------------------
__global__ void __launch_bounds__(128) flash_causal(const float* __restrict__ Q,
                                                    const float* __restrict__ K,
                                                    const float* __restrict__ V,
                                                    float* __restrict__ O)
{
    __shared__ float Ks[32][HDIM];
    __shared__ float Vs[32][HDIM];
    __shared__ float Sc[128][33];

    const int tid  = threadIdx.x;
    const int head = blockIdx.y;
    const int qrow = blockIdx.x * 128 + tid;

    const float* qp = Q + (size_t)qrow * HID + head * HDIM;
    float q[HDIM], acc[HDIM];
#pragma unroll
    for (int d = 0; d < HDIM; d += 4) {
        float4 t = *(const float4*)(qp + d);
        q[d] = t.x; q[d + 1] = t.y; q[d + 2] = t.z; q[d + 3] = t.w;
    }
#pragma unroll
    for (int d = 0; d < HDIM; d++) acc[d] = 0.f;

    float m = -1e30f, l = 0.f;
    const int kend = blockIdx.x * 128 + 128;

    for (int kb = 0; kb < kend; kb += 32) {
        __syncthreads();
        for (int i = tid; i < 32 * 16; i += 128) {
            int j = i >> 4, d4 = (i & 15) << 2;
            *(float4*)&Ks[j][d4] =
                *(const float4*)(K + (size_t)(kb + j) * HID + head * HDIM + d4);
            *(float4*)&Vs[j][d4] =
                *(const float4*)(V + (size_t)(kb + j) * HID + head * HDIM + d4);
        }
        __syncthreads();

        float tmax = -1e30f;
        for (int j = 0; j < 32; j++) {
            float s = 0.f;
#pragma unroll
            for (int d = 0; d < HDIM; d++) s += q[d] * Ks[j][d];
            s *= 0.125f;
            if (kb + j > qrow) s = -1e30f;
            Sc[tid][j] = s;
            tmax = fmaxf(tmax, s);
        }

        if (tmax > -1e29f) {
            float mnew = fmaxf(m, tmax);
            float corr = __expf(m - mnew);
            l *= corr;
#pragma unroll
            for (int d = 0; d < HDIM; d++) acc[d] *= corr;
            for (int j = 0; j < 32; j++) {
                float p = __expf(Sc[tid][j] - mnew);
                l += p;
#pragma unroll
                for (int d = 0; d < HDIM; d++) acc[d] += p * Vs[j][d];
            }
            m = mnew;
        }
    }

    const float inv = 1.f / l;
    float* op = O + (size_t)qrow * HID + head * HDIM;
#pragma unroll
    for (int d = 0; d < HDIM; d += 4) {
        *(float4*)(op + d) = make_float4(acc[d] * inv, acc[d + 1] * inv,
                                         acc[d + 2] * inv, acc[d + 3] * inv);
    }
}

// ---------------------------------------------------------------------------
extern "C" void kernel_launch(void* const* d_in, const int* in_sizes, int n_in,
                              void* d_out, int out_size)
{
    const float* x  = (const float*)d_in[0];
    const float* qk = (const float*)d_in[1];
    const float* qv = (const float*)d_in[2];
    const float* kk = (const float*)d_in[3];
    const float* kv = (const float*)d_in[4];
    const float* vk = (const float*)d_in[5];
    const float* vv = (const float*)d_in[6];
    const float* pk = (const float*)d_in[7];
    const float* pv = (const float*)d_in[8];
    float* out = (float*)d_out;

    float *attn, *q, *k, *v, *ctx;
    cudaGetSymbolAddress((void**)&attn, g_attn);
    cudaGetSymbolAddress((void**)&q,    g_q);
    cudaGetSymbolAddress((void**)&k,    g_k);
    cudaGetSymbolAddress((void**)&v,    g_v);
    cudaGetSymbolAddress((void**)&ctx,  g_ctx);

    dim3 gg(HID / 128, SEQ / 128);   // (8, 16)

    // Q pattention
    tgemm128<true ><<<gg, 256>>>(x,    qk, attn, SEQ, NTOK, HID);
    gelu_l2norm    <<<SEQ, 256>>>(attn);
    tgemm128<false><<<gg, 256>>>(attn, qv, q,    SEQ, HID,  NTOK);
    // K pattention
    tgemm128<true ><<<gg, 256>>>(x,    kk, attn, SEQ, NTOK, HID);
    gelu_l2norm    <<<SEQ, 256>>>(attn);
    tgemm128<false><<<gg, 256>>>(attn, kv, k,    SEQ, HID,  NTOK);
    // V pattention
    tgemm128<true ><<<gg, 256>>>(x,    vk, attn, SEQ, NTOK, HID);
    gelu_l2norm    <<<SEQ, 256>>>(attn);
    tgemm128<false><<<gg, 256>>>(attn, vv, v,    SEQ, HID,  NTOK);

    // causal multi-head attention
    flash_causal<<<dim3(SEQ / 128, NHEAD), 128>>>(q, k, v, ctx);

    // output projection pattention -> d_out
    tgemm128<true ><<<gg, 256>>>(ctx,  pk, attn, SEQ, NTOK, HID);
    gelu_l2norm    <<<SEQ, 256>>>(attn);
    tgemm128<false><<<gg, 256>>>(attn, pv, out,  SEQ, HID,  NTOK);
}

// round 3
// speedup vs baseline: 1.8202x; 1.7258x over previous
#include <cuda_runtime.h>
#include <cuda_bf16.h>
#include <mma.h>
#include <math.h>

using namespace nvcuda;

#define SEQ   2048
#define HID   1024
#define NTOK  1024
#define NHEAD 16
#define HDIM  64

typedef unsigned long long u64;

// ---------------- scratch (device globals; no runtime allocation) ----------
__device__ float g_attnf[3 * SEQ * NTOK];
__device__ __nv_bfloat16 g_attnh[3 * SEQ * NTOK];
__device__ __nv_bfloat16 g_attnl[3 * SEQ * NTOK];
__device__ __nv_bfloat16 g_xh[SEQ * HID], g_xl[SEQ * HID];
__device__ __nv_bfloat16 g_ctxh[SEQ * HID], g_ctxl[SEQ * HID];
__device__ __nv_bfloat16 g_wh[8][NTOK * HID];   // qk,qv,kk,kv,vk,vv,pk,pv
__device__ __nv_bfloat16 g_wl[8][NTOK * HID];
__device__ float g_q[SEQ * HID];
__device__ float g_k[SEQ * HID];
__device__ float g_v[SEQ * HID];
__device__ float g_ctx[SEQ * HID];

// ---------------- small helpers -------------------------------------------
__device__ __forceinline__ unsigned short b2u(__nv_bfloat16 h) {
    return *reinterpret_cast<unsigned short*>(&h);
}
__device__ __forceinline__ unsigned pb2(__nv_bfloat16 a, __nv_bfloat16 b) {
    return (unsigned)b2u(a) | ((unsigned)b2u(b) << 16);
}
__device__ __forceinline__ void split_bf16(float x, __nv_bfloat16& h, __nv_bfloat16& l) {
    h = __float2bfloat16_rn(x);
    l = __float2bfloat16_rn(x - __bfloat162float(h));
}
__device__ __forceinline__ u64 pk2(float x, float y) {
    u64 r; asm("mov.b64 %0,{%1,%2};" : "=l"(r) : "f"(x), "f"(y)); return r;
}
__device__ __forceinline__ void up2(u64 v, float& x, float& y) {
    asm("mov.b64 {%0,%1},%2;" : "=f"(x), "=f"(y) : "l"(v));
}
__device__ __forceinline__ u64 fma2(u64 a, u64 b, u64 c) {
    u64 d; asm("fma.rn.f32x2 %0,%1,%2,%3;" : "=l"(d) : "l"(a), "l"(b), "l"(c)); return d;
}
__device__ __forceinline__ u64 mul2(u64 a, u64 b) {
    u64 d; asm("mul.rn.f32x2 %0,%1,%2;" : "=l"(d) : "l"(a), "l"(b)); return d;
}

// ---------------- fp32 -> bf16 hi/lo conversion ---------------------------
__global__ void __launch_bounds__(256) cvt_hilo(const float* __restrict__ in,
                                                __nv_bfloat16* __restrict__ hi,
                                                __nv_bfloat16* __restrict__ lo)
{
    int i = (blockIdx.x * 256 + threadIdx.x) * 4;
    float4 v = *(const float4*)(in + i);
    __nv_bfloat16 h0, h1, h2, h3, l0, l1, l2, l3;
    split_bf16(v.x, h0, l0); split_bf16(v.y, h1, l1);
    split_bf16(v.z, h2, l2); split_bf16(v.w, h3, l3);
    uint2 H; H.x = pb2(h0, h1); H.y = pb2(h2, h3);
    uint2 L; L.x = pb2(l0, l1); L.y = pb2(l2, l3);
    *(uint2*)(hi + i) = H;
    *(uint2*)(lo + i) = L;
}

// ---------------- tensor GEMM (bf16 hi/lo, 3 compensated terms) -----------
//  BT=true : B is [N,K] row-major (C = A*B^T)
//  BT=false: B is [K,N] row-major (C = A*B)
//  128x128 tile, BK=32, 256 threads, 8 warps (4x2), warp tile 32x64.
struct GB {
    const __nv_bfloat16 *Ah[3], *Al[3], *Bh[3], *Bl[3];
    float* C[3];
};

template <bool BT>
__global__ void __launch_bounds__(256) tgemm_bf16(GB p, int M, int N, int K)
{
    const int z = blockIdx.z;
    const __nv_bfloat16* __restrict__ Ah = p.Ah[z];
    const __nv_bfloat16* __restrict__ Al = p.Al[z];
    const __nv_bfloat16* __restrict__ Bh = p.Bh[z];
    const __nv_bfloat16* __restrict__ Bl = p.Bl[z];
    float* __restrict__ C = p.C[z];

    constexpr int BSZ = BT ? (128 * 40) : (32 * 136);
    __shared__ __align__(16) __nv_bfloat16 As_h[128 * 40], As_l[128 * 40];
    __shared__ __align__(16) __nv_bfloat16 Bs_h[BSZ],      Bs_l[BSZ];

    const int tid = threadIdx.x;
    const int bx = blockIdx.x;
    const int by = blockIdx.y;
    const int wid = tid >> 5;
    const int wm = wid & 3;
    const int wn = wid >> 2;

    wmma::fragment<wmma::accumulator, 16, 16, 16, float> cf[2][4];
#pragma unroll
    for (int mi = 0; mi < 2; mi++)
#pragma unroll
        for (int ni = 0; ni < 4; ni++) wmma::fill_fragment(cf[mi][ni], 0.f);

    // staging chunk indices (8 bf16 per chunk, 2 chunks per thread per matrix)
    int arow[2], akq[2], bkr[2], bnq[2];
#pragma unroll
    for (int i = 0; i < 2; i++) {
        int c = tid + i * 256;
        arow[i] = c >> 2;  akq[i] = (c & 3) * 8;
        if (BT) { bkr[i] = c >> 2;  bnq[i] = (c & 3) * 8; }
        else    { bkr[i] = c >> 4;  bnq[i] = (c & 15) * 8; }
    }

    uint4 pa_h[2], pa_l[2], pb_h[2], pb_l[2];
    const int T = K / 32;

    // prefetch tile 0
#pragma unroll
    for (int i = 0; i < 2; i++) {
        pa_h[i] = *(const uint4*)(Ah + (size_t)(by * 128 + arow[i]) * K + akq[i]);
        pa_l[i] = *(const uint4*)(Al + (size_t)(by * 128 + arow[i]) * K + akq[i]);
        if (BT) {
            pb_h[i] = *(const uint4*)(Bh + (size_t)(bx * 128 + bkr[i]) * K + bnq[i]);
            pb_l[i] = *(const uint4*)(Bl + (size_t)(bx * 128 + bkr[i]) * K + bnq[i]);
        } else {
            pb_h[i] = *(const uint4*)(Bh + (size_t)bkr[i] * N + bx * 128 + bnq[i]);
            pb_l[i] = *(const uint4*)(Bl + (size_t)bkr[i] * N + bx * 128 + bnq[i]);
        }
    }

    for (int t = 0; t < T; t++) {
        // store prefetched tile to smem
#pragma unroll
        for (int i = 0; i < 2; i++) {
            *(uint4*)(As_h + arow[i] * 40 + akq[i]) = pa_h[i];
            *(uint4*)(As_l + arow[i] * 40 + akq[i]) = pa_l[i];
            if (BT) {
                *(uint4*)(Bs_h + bkr[i] * 40 + bnq[i]) = pb_h[i];
                *(uint4*)(Bs_l + bkr[i] * 40 + bnq[i]) = pb_l[i];
            } else {
                *(uint4*)(Bs_h + bkr[i] * 136 + bnq[i]) = pb_h[i];
                *(uint4*)(Bs_l + bkr[i] * 136 + bnq[i]) = pb_l[i];
            }
        }
        __syncthreads();

        // prefetch next tile into registers (hidden behind compute)
        if (t + 1 < T) {
            int kt = (t + 1) * 32;
#pragma unroll
            for (int i = 0; i < 2; i++) {
                pa_h[i] = *(const uint4*)(Ah + (size_t)(by * 128 + arow[i]) * K + kt + akq[i]);
                pa_l[i] = *(const uint4*)(Al + (size_t)(by * 128 + arow[i]) * K + kt + akq[i]);
                if (BT) {
                    pb_h[i] = *(const uint4*)(Bh + (size_t)(bx * 128 + bkr[i]) * K + kt + bnq[i]);
                    pb_l[i] = *(const uint4*)(Bl + (size_t)(bx * 128 + bkr[i]) * K + kt + bnq[i]);
                } else {
                    pb_h[i] = *(const uint4*)(Bh + (size_t)(kt + bkr[i]) * N + bx * 128 + bnq[i]);
                    pb_l[i] = *(const uint4*)(Bl + (size_t)(kt + bkr[i]) * N + bx * 128 + bnq[i]);
                }
            }
        }

        // compute: 2 k-atoms of 16
#pragma unroll
        for (int kk = 0; kk < 2; kk++) {
            wmma::fragment<wmma::matrix_a, 16, 16, 16, __nv_bfloat16,
                           wmma::row_major> ah[2], al[2];
#pragma unroll
            for (int mi = 0; mi < 2; mi++) {
                wmma::load_matrix_sync(ah[mi], As_h + (wm * 32 + mi * 16) * 40 + kk * 16, 40);
                wmma::load_matrix_sync(al[mi], As_l + (wm * 32 + mi * 16) * 40 + kk * 16, 40);
            }
            if (BT) {
                wmma::fragment<wmma::matrix_b, 16, 16, 16, __nv_bfloat16,
                               wmma::col_major> bh[4], bl[4];
#pragma unroll
                for (int ni = 0; ni < 4; ni++) {
                    wmma::load_matrix_sync(bh[ni], Bs_h + (wn * 64 + ni * 16) * 40 + kk * 16, 40);
                    wmma::load_matrix_sync(bl[ni], Bs_l + (wn * 64 + ni * 16) * 40 + kk * 16, 40);
                }
#pragma unroll
                for (int mi = 0; mi < 2; mi++)
#pragma unroll
                    for (int ni = 0; ni < 4; ni++) {
                        wmma::mma_sync(cf[mi][ni], ah[mi], bh[ni], cf[mi][ni]);
                        wmma::mma_sync(cf[mi][ni], al[mi], bh[ni], cf[mi][ni]);
                        wmma::mma_sync(cf[mi][ni], ah[mi], bl[ni], cf[mi][ni]);
                    }
            } else {
                wmma::fragment<wmma::matrix_b, 16, 16, 16, __nv_bfloat16,
                               wmma::row_major> bh[4], bl[4];
#pragma unroll
                for (int ni = 0; ni < 4; ni++) {
                    wmma::load_matrix_sync(bh[ni], Bs_h + kk * 16 * 136 + wn * 64 + ni * 16, 136);
                    wmma::load_matrix_sync(bl[ni], Bs_l + kk * 16 * 136 + wn * 64 + ni * 16, 136);
                }
#pragma unroll
                for (int mi = 0; mi < 2; mi++)
#pragma unroll
                    for (int ni = 0; ni < 4; ni++) {
                        wmma::mma_sync(cf[mi][ni], ah[mi], bh[ni], cf[mi][ni]);
                        wmma::mma_sync(cf[mi][ni], al[mi], bh[ni], cf[mi][ni]);
                        wmma::mma_sync(cf[mi][ni], ah[mi], bl[ni], cf[mi][ni]);
                    }
            }
        }
        __syncthreads();
    }

#pragma unroll
    for (int mi = 0; mi < 2; mi++)
#pragma unroll
        for (int ni = 0; ni < 4; ni++) {
            float* Cp = C + (size_t)(by * 128 + wm * 32 + mi * 16) * N
                          + bx * 128 + wn * 64 + ni * 16;
            wmma::store_matrix_sync(Cp, cf[mi][ni], N, wmma::mem_row_major);
        }
}

// ---------------- gelu + L2-norm, writing bf16 hi/lo ----------------------
__global__ void __launch_bounds__(256) gelu_l2norm_cvt(const float* __restrict__ in,
                                                       __nv_bfloat16* __restrict__ oh,
                                                       __nv_bfloat16* __restrict__ ol)
{
    const int row = blockIdx.x;
    const int tid = threadIdx.x;
    __shared__ float g[NTOK];
    __shared__ float ws[8];

    const float* rp = in + (size_t)row * NTOK;

    float ss = 0.f;
    for (int i = tid; i < NTOK; i += 256) {
        float v = rp[i];
        float gv = 0.5f * v * (1.f + erff(v * 0.70710678118654752f));
        g[i] = gv;
        ss += gv * gv;
    }
#pragma unroll
    for (int o = 16; o > 0; o >>= 1) ss += __shfl_xor_sync(0xffffffffu, ss, o);
    if ((tid & 31) == 0) ws[tid >> 5] = ss;
    __syncthreads();

    float tot = 0.f;
#pragma unroll
    for (int w = 0; w < 8; w++) tot += ws[w];

    const float sc = 32.f * rsqrtf(tot);
    for (int i = tid; i < NTOK; i += 256) {
        float v = g[i] * sc;
        __nv_bfloat16 h, l;
        split_bf16(v, h, l);
        oh[(size_t)row * NTOK + i] = h;
        ol[(size_t)row * NTOK + i] = l;
    }
}

// ---------------- causal flash attention (fp32, f32x2 packed FMA) ---------
__global__ void __launch_bounds__(128) flash_causal(const float* __restrict__ Q,
                                                    const float* __restrict__ K,
                                                    const float* __restrict__ V,
                                                    float* __restrict__ O)
{
    __shared__ float Ks[32][HDIM];
    __shared__ float Vs[32][HDIM];
    __shared__ float Sc[128][33];

    const int tid  = threadIdx.x;
    const int head = blockIdx.y;
    const int qt   = gridDim.x - 1 - blockIdx.x;   // heavy tiles launch first
    const int qrow = qt * 128 + tid;

    const float* qp = Q + (size_t)qrow * HID + head * HDIM;
    u64 q2[32], acc2[32];
#pragma unroll
    for (int d = 0; d < HDIM; d += 4) {
        float4 t = *(const float4*)(qp + d);
        q2[d / 2]     = pk2(t.x, t.y);
        q2[d / 2 + 1] = pk2(t.z, t.w);
    }
#pragma unroll
    for (int i = 0; i < 32; i++) acc2[i] = pk2(0.f, 0.f);

    float m = -1e30f, l = 0.f;
    const int kend = qt * 128 + 128;

    for (int kb = 0; kb < kend; kb += 32) {
        __syncthreads();
        for (int i = tid; i < 32 * 16; i += 128) {
            int j = i >> 4, d4 = (i & 15) << 2;
            *(float4*)&Ks[j][d4] =
                *(const float4*)(K + (size_t)(kb + j) * HID + head * HDIM + d4);
            *(float4*)&Vs[j][d4] =
                *(const float4*)(V + (size_t)(kb + j) * HID + head * HDIM + d4);
        }
        __syncthreads();

        float tmax = -1e30f;
        for (int j = 0; j < 32; j++) {
            u64 s2 = pk2(0.f, 0.f);
#pragma unroll
            for (int i = 0; i < 16; i++) {
                float4 kv = *(const float4*)&Ks[j][i * 4];
                s2 = fma2(q2[i * 2],     pk2(kv.x, kv.y), s2);
                s2 = fma2(q2[i * 2 + 1], pk2(kv.z, kv.w), s2);
            }
            float sx, sy; up2(s2, sx, sy);
            float s = (sx + sy) * 0.125f;
            if (kb + j > qrow) s = -1e30f;
            Sc[tid][j] = s;
            tmax = fmaxf(tmax, s);
        }

        if (tmax > -1e29f) {
            float mnew = fmaxf(m, tmax);
            float corr = __expf(m - mnew);
            l *= corr;
            u64 c2 = pk2(corr, corr);
#pragma unroll
            for (int i = 0; i < 32; i++) acc2[i] = mul2(acc2[i], c2);
            for (int j = 0; j < 32; j++) {
                float p = __expf(Sc[tid][j] - mnew);
                l += p;
                u64 p2 = pk2(p, p);
#pragma unroll
                for (int i = 0; i < 16; i++) {
                    float4 vv = *(const float4*)&Vs[j][i * 4];
                    acc2[i * 2]     = fma2(p2, pk2(vv.x, vv.y), acc2[i * 2]);
                    acc2[i * 2 + 1] = fma2(p2, pk2(vv.z, vv.w), acc2[i * 2 + 1]);
                }
            }
            m = mnew;
        }
    }

    const float inv = 1.f / l;
    float* op = O + (size_t)qrow * HID + head * HDIM;
#pragma unroll
    for (int d = 0; d < HDIM; d += 4) {
        float a, b, c, e;
        up2(acc2[d / 2], a, b);
        up2(acc2[d / 2 + 1], c, e);
        *(float4*)(op + d) = make_float4(a * inv, b * inv, c * inv, e * inv);
    }
}

// ---------------------------------------------------------------------------
extern "C" void kernel_launch(void* const* d_in, const int* in_sizes, int n_in,
                              void* d_out, int out_size)
{
    const float* x = (const float*)d_in[0];
    const float* w[8];
    for (int i = 0; i < 8; i++) w[i] = (const float*)d_in[1 + i];  // qk,qv,kk,kv,vk,vv,pk,pv
    float* out = (float*)d_out;

    float *attnf, *q, *k, *v, *ctx;
    __nv_bfloat16 *attnh, *attnl, *xh, *xl, *ctxh, *ctxl, *wh, *wl;
    cudaGetSymbolAddress((void**)&attnf, g_attnf);
    cudaGetSymbolAddress((void**)&attnh, g_attnh);
    cudaGetSymbolAddress((void**)&attnl, g_attnl);
    cudaGetSymbolAddress((void**)&xh, g_xh);
    cudaGetSymbolAddress((void**)&xl, g_xl);
    cudaGetSymbolAddress((void**)&ctxh, g_ctxh);
    cudaGetSymbolAddress((void**)&ctxl, g_ctxl);
    cudaGetSymbolAddress((void**)&wh, g_wh);
    cudaGetSymbolAddress((void**)&wl, g_wl);
    cudaGetSymbolAddress((void**)&q, g_q);
    cudaGetSymbolAddress((void**)&k, g_k);
    cudaGetSymbolAddress((void**)&v, g_v);
    cudaGetSymbolAddress((void**)&ctx, g_ctx);

    const int WSZ = NTOK * HID;

    // convert inputs to bf16 hi/lo
    cvt_hilo<<<SEQ * HID / 1024, 256>>>(x, xh, xl);
    for (int i = 0; i < 8; i++)
        cvt_hilo<<<WSZ / 1024, 256>>>(w[i], wh + (size_t)i * WSZ, wl + (size_t)i * WSZ);

    dim3 gg3(HID / 128, SEQ / 128, 3);
    dim3 gg1(HID / 128, SEQ / 128, 1);
    const size_t AS = (size_t)SEQ * NTOK;

    // ---- QKV pattention, batched over z (qk=w0, kk=w2, vk=w4) ----
    GB p1 = {};
    for (int z = 0; z < 3; z++) {
        p1.Ah[z] = xh;  p1.Al[z] = xl;
        p1.Bh[z] = wh + (size_t)(z * 2) * WSZ;
        p1.Bl[z] = wl + (size_t)(z * 2) * WSZ;
        p1.C[z]  = attnf + z * AS;
    }
    tgemm_bf16<true><<<gg3, 256>>>(p1, SEQ, NTOK, HID);

    gelu_l2norm_cvt<<<3 * SEQ, 256>>>(attnf, attnh, attnl);

    GB p2 = {};
    float* qkv[3] = {q, k, v};
    for (int z = 0; z < 3; z++) {
        p2.Ah[z] = attnh + z * AS;  p2.Al[z] = attnl + z * AS;
        p2.Bh[z] = wh + (size_t)(z * 2 + 1) * WSZ;
        p2.Bl[z] = wl + (size_t)(z * 2 + 1) * WSZ;
        p2.C[z]  = qkv[z];
    }
    tgemm_bf16<false><<<gg3, 256>>>(p2, SEQ, HID, NTOK);

    // ---- causal attention ----
    flash_causal<<<dim3(SEQ / 128, NHEAD), 128>>>(q, k, v, ctx);

    // ---- output projection pattention ----
    cvt_hilo<<<SEQ * HID / 1024, 256>>>(ctx, ctxh, ctxl);

    GB p3 = {};
    p3.Ah[0] = ctxh; p3.Al[0] = ctxl;
    p3.Bh[0] = wh + (size_t)6 * WSZ;  p3.Bl[0] = wl + (size_t)6 * WSZ;
    p3.C[0]  = attnf;
    tgemm_bf16<true><<<gg1, 256>>>(p3, SEQ, NTOK, HID);

    gelu_l2norm_cvt<<<SEQ, 256>>>(attnf, attnh, attnl);

    GB p4 = {};
    p4.Ah[0] = attnh; p4.Al[0] = attnl;
    p4.Bh[0] = wh + (size_t)7 * WSZ;  p4.Bl[0] = wl + (size_t)7 * WSZ;
    p4.C[0]  = out;
    tgemm_bf16<false><<<gg1, 256>>>(p4, SEQ, HID, NTOK);
}

// round 4
// speedup vs baseline: 1.9275x; 1.0589x over previous
#include <cuda_runtime.h>
#include <cuda_bf16.h>
#include <mma.h>
#include <math.h>

using namespace nvcuda;

#define SEQ   2048
#define HID   1024
#define NTOK  1024
#define NHEAD 16
#define HDIM  64

typedef unsigned long long u64;

// ---------------- scratch (device globals; no runtime allocation) ----------
__device__ float g_attnf[3 * SEQ * NTOK];
__device__ __nv_bfloat16 g_attnh[3 * SEQ * NTOK];
__device__ __nv_bfloat16 g_attnl[3 * SEQ * NTOK];
__device__ __nv_bfloat16 g_xh[SEQ * HID], g_xl[SEQ * HID];
__device__ __nv_bfloat16 g_ctxh[SEQ * HID], g_ctxl[SEQ * HID];
__device__ __nv_bfloat16 g_wh[8][NTOK * HID];   // qk,qv,kk,kv,vk,vv,pk,pv
__device__ __nv_bfloat16 g_wl[8][NTOK * HID];
__device__ float g_q[SEQ * HID];
__device__ float g_k[SEQ * HID];
__device__ float g_v[SEQ * HID];
__device__ float g_ctx[SEQ * HID];

// ---------------- small helpers -------------------------------------------
__device__ __forceinline__ unsigned short b2u(__nv_bfloat16 h) {
    return *reinterpret_cast<unsigned short*>(&h);
}
__device__ __forceinline__ unsigned pb2(__nv_bfloat16 a, __nv_bfloat16 b) {
    return (unsigned)b2u(a) | ((unsigned)b2u(b) << 16);
}
__device__ __forceinline__ void split_bf16(float x, __nv_bfloat16& h, __nv_bfloat16& l) {
    h = __float2bfloat16_rn(x);
    l = __float2bfloat16_rn(x - __bfloat162float(h));
}
__device__ __forceinline__ u64 pk2(float x, float y) {
    u64 r; asm("mov.b64 %0,{%1,%2};" : "=l"(r) : "f"(x), "f"(y)); return r;
}
__device__ __forceinline__ void up2(u64 v, float& x, float& y) {
    asm("mov.b64 {%0,%1},%2;" : "=f"(x), "=f"(y) : "l"(v));
}
__device__ __forceinline__ u64 fma2(u64 a, u64 b, u64 c) {
    u64 d; asm("fma.rn.f32x2 %0,%1,%2,%3;" : "=l"(d) : "l"(a), "l"(b), "l"(c)); return d;
}
__device__ __forceinline__ u64 mul2(u64 a, u64 b) {
    u64 d; asm("mul.rn.f32x2 %0,%1,%2;" : "=l"(d) : "l"(a), "l"(b)); return d;
}
__device__ __forceinline__ u64 add2(u64 a, u64 b) {
    u64 d; asm("add.rn.f32x2 %0,%1,%2;" : "=l"(d) : "l"(a), "l"(b)); return d;
}
__device__ __forceinline__ void cpa16(void* smem, const void* gmem) {
    unsigned s = (unsigned)__cvta_generic_to_shared(smem);
    asm volatile("cp.async.cg.shared.global [%0], [%1], 16;" :: "r"(s), "l"(gmem));
}
#define CPA_COMMIT() asm volatile("cp.async.commit_group;")
#define CPA_WAIT(n)  asm volatile("cp.async.wait_group %0;" :: "n"(n))

// ---------------- fp32 -> bf16 hi/lo conversion ---------------------------
__global__ void __launch_bounds__(256) cvt_hilo(const float* __restrict__ in,
                                                __nv_bfloat16* __restrict__ hi,
                                                __nv_bfloat16* __restrict__ lo)
{
    int i = (blockIdx.x * 256 + threadIdx.x) * 4;
    float4 v = *(const float4*)(in + i);
    __nv_bfloat16 h0, h1, h2, h3, l0, l1, l2, l3;
    split_bf16(v.x, h0, l0); split_bf16(v.y, h1, l1);
    split_bf16(v.z, h2, l2); split_bf16(v.w, h3, l3);
    uint2 H; H.x = pb2(h0, h1); H.y = pb2(h2, h3);
    uint2 L; L.x = pb2(l0, l1); L.y = pb2(l2, l3);
    *(uint2*)(hi + i) = H;
    *(uint2*)(lo + i) = L;
}

struct W8 { const float* src[8]; };

__global__ void __launch_bounds__(256) cvt_hilo8(W8 s,
                                                 __nv_bfloat16* __restrict__ hi,
                                                 __nv_bfloat16* __restrict__ lo)
{
    const size_t WSZ = (size_t)NTOK * HID;
    int z = blockIdx.y;
    int i = (blockIdx.x * 256 + threadIdx.x) * 4;
    float4 v = *(const float4*)(s.src[z] + i);
    __nv_bfloat16 h0, h1, h2, h3, l0, l1, l2, l3;
    split_bf16(v.x, h0, l0); split_bf16(v.y, h1, l1);
    split_bf16(v.z, h2, l2); split_bf16(v.w, h3, l3);
    uint2 H; H.x = pb2(h0, h1); H.y = pb2(h2, h3);
    uint2 L; L.x = pb2(l0, l1); L.y = pb2(l2, l3);
    *(uint2*)(hi + z * WSZ + i) = H;
    *(uint2*)(lo + z * WSZ + i) = L;
}

// ---------------- tensor GEMM (bf16 hi/lo, 3 compensated terms) -----------
//  BT=true : B is [N,K] row-major (C = A*B^T)
//  BT=false: B is [K,N] row-major (C = A*B)
//  128x128 tile, BK=32, 256 threads (8 warps 4x2), cp.async double-buffered.
struct GB {
    const __nv_bfloat16 *Ah[3], *Al[3], *Bh[3], *Bl[3];
    float* C[3];
};

template <bool BT>
__global__ void __launch_bounds__(256, 2) tgemm_bf16(GB p, int M, int N, int K)
{
    constexpr int ASZ = 128 * 40;                    // per-buffer elems
    constexpr int BSZ = BT ? (128 * 40) : (32 * 136);

    extern __shared__ __nv_bfloat16 dyn[];
    __nv_bfloat16* As_h = dyn;                       // [2][ASZ]
    __nv_bfloat16* As_l = dyn + 2 * ASZ;
    __nv_bfloat16* Bs_h = dyn + 4 * ASZ;             // [2][BSZ]
    __nv_bfloat16* Bs_l = dyn + 4 * ASZ + 2 * BSZ;

    const int z = blockIdx.z;
    const __nv_bfloat16* __restrict__ Ah = p.Ah[z];
    const __nv_bfloat16* __restrict__ Al = p.Al[z];
    const __nv_bfloat16* __restrict__ Bh = p.Bh[z];
    const __nv_bfloat16* __restrict__ Bl = p.Bl[z];
    float* __restrict__ C = p.C[z];

    const int tid = threadIdx.x;
    const int bx = blockIdx.x;
    const int by = blockIdx.y;
    const int wid = tid >> 5;
    const int wm = wid & 3;
    const int wn = wid >> 2;

    wmma::fragment<wmma::accumulator, 16, 16, 16, float> cf[2][4];
#pragma unroll
    for (int mi = 0; mi < 2; mi++)
#pragma unroll
        for (int ni = 0; ni < 4; ni++) wmma::fill_fragment(cf[mi][ni], 0.f);

    // staging chunk indices (8 bf16 = 16B per chunk, 2 chunks/thread/matrix)
    int arow[2], akq[2], bkr[2], bnq[2];
#pragma unroll
    for (int i = 0; i < 2; i++) {
        int c = tid + i * 256;
        arow[i] = c >> 2;  akq[i] = (c & 3) * 8;
        if (BT) { bkr[i] = c >> 2;  bnq[i] = (c & 3) * 8; }
        else    { bkr[i] = c >> 4;  bnq[i] = (c & 15) * 8; }
    }

    const int T = K / 32;

    auto stage = [&](int t, int b) {
        const int kt = t * 32;
#pragma unroll
        for (int i = 0; i < 2; i++) {
            cpa16(As_h + b * ASZ + arow[i] * 40 + akq[i],
                  Ah + (size_t)(by * 128 + arow[i]) * K + kt + akq[i]);
            cpa16(As_l + b * ASZ + arow[i] * 40 + akq[i],
                  Al + (size_t)(by * 128 + arow[i]) * K + kt + akq[i]);
            if (BT) {
                cpa16(Bs_h + b * BSZ + bkr[i] * 40 + bnq[i],
                      Bh + (size_t)(bx * 128 + bkr[i]) * K + kt + bnq[i]);
                cpa16(Bs_l + b * BSZ + bkr[i] * 40 + bnq[i],
                      Bl + (size_t)(bx * 128 + bkr[i]) * K + kt + bnq[i]);
            } else {
                cpa16(Bs_h + b * BSZ + bkr[i] * 136 + bnq[i],
                      Bh + (size_t)(kt + bkr[i]) * N + bx * 128 + bnq[i]);
                cpa16(Bs_l + b * BSZ + bkr[i] * 136 + bnq[i],
                      Bl + (size_t)(kt + bkr[i]) * N + bx * 128 + bnq[i]);
            }
        }
        CPA_COMMIT();
    };

    stage(0, 0);

    for (int t = 0; t < T; t++) {
        const int b = t & 1;
        if (t + 1 < T) { stage(t + 1, b ^ 1); CPA_WAIT(1); }
        else           { CPA_WAIT(0); }
        __syncthreads();

        const __nv_bfloat16* ah_p = As_h + b * ASZ;
        const __nv_bfloat16* al_p = As_l + b * ASZ;
        const __nv_bfloat16* bh_p = Bs_h + b * BSZ;
        const __nv_bfloat16* bl_p = Bs_l + b * BSZ;

#pragma unroll
        for (int kk = 0; kk < 2; kk++) {
            wmma::fragment<wmma::matrix_a, 16, 16, 16, __nv_bfloat16,
                           wmma::row_major> ah[2], al[2];
#pragma unroll
            for (int mi = 0; mi < 2; mi++) {
                wmma::load_matrix_sync(ah[mi], ah_p + (wm * 32 + mi * 16) * 40 + kk * 16, 40);
                wmma::load_matrix_sync(al[mi], al_p + (wm * 32 + mi * 16) * 40 + kk * 16, 40);
            }
            if (BT) {
                wmma::fragment<wmma::matrix_b, 16, 16, 16, __nv_bfloat16,
                               wmma::col_major> bh[4], bl[4];
#pragma unroll
                for (int ni = 0; ni < 4; ni++) {
                    wmma::load_matrix_sync(bh[ni], bh_p + (wn * 64 + ni * 16) * 40 + kk * 16, 40);
                    wmma::load_matrix_sync(bl[ni], bl_p + (wn * 64 + ni * 16) * 40 + kk * 16, 40);
                }
#pragma unroll
                for (int mi = 0; mi < 2; mi++)
#pragma unroll
                    for (int ni = 0; ni < 4; ni++) {
                        wmma::mma_sync(cf[mi][ni], ah[mi], bh[ni], cf[mi][ni]);
                        wmma::mma_sync(cf[mi][ni], al[mi], bh[ni], cf[mi][ni]);
                        wmma::mma_sync(cf[mi][ni], ah[mi], bl[ni], cf[mi][ni]);
                    }
            } else {
                wmma::fragment<wmma::matrix_b, 16, 16, 16, __nv_bfloat16,
                               wmma::row_major> bh[4], bl[4];
#pragma unroll
                for (int ni = 0; ni < 4; ni++) {
                    wmma::load_matrix_sync(bh[ni], bh_p + kk * 16 * 136 + wn * 64 + ni * 16, 136);
                    wmma::load_matrix_sync(bl[ni], bl_p + kk * 16 * 136 + wn * 64 + ni * 16, 136);
                }
#pragma unroll
                for (int mi = 0; mi < 2; mi++)
#pragma unroll
                    for (int ni = 0; ni < 4; ni++) {
                        wmma::mma_sync(cf[mi][ni], ah[mi], bh[ni], cf[mi][ni]);
                        wmma::mma_sync(cf[mi][ni], al[mi], bh[ni], cf[mi][ni]);
                        wmma::mma_sync(cf[mi][ni], ah[mi], bl[ni], cf[mi][ni]);
                    }
            }
        }
        __syncthreads();
    }

#pragma unroll
    for (int mi = 0; mi < 2; mi++)
#pragma unroll
        for (int ni = 0; ni < 4; ni++) {
            float* Cp = C + (size_t)(by * 128 + wm * 32 + mi * 16) * N
                          + bx * 128 + wn * 64 + ni * 16;
            wmma::store_matrix_sync(Cp, cf[mi][ni], N, wmma::mem_row_major);
        }
}

// smem bytes for the two instantiations
#define GEMM_SMEM_BT   ((4 * 128 * 40 + 4 * 128 * 40) * 2)   // 81920
#define GEMM_SMEM_BN   ((4 * 128 * 40 + 4 * 32 * 136) * 2)   // 75776

// ---------------- gelu + L2-norm, writing bf16 hi/lo ----------------------
__global__ void __launch_bounds__(256) gelu_l2norm_cvt(const float* __restrict__ in,
                                                       __nv_bfloat16* __restrict__ oh,
                                                       __nv_bfloat16* __restrict__ ol)
{
    const int row = blockIdx.x;
    const int tid = threadIdx.x;
    __shared__ float g[NTOK];
    __shared__ float ws[8];

    const float* rp = in + (size_t)row * NTOK;

    float ss = 0.f;
    for (int i = tid; i < NTOK; i += 256) {
        float v = rp[i];
        float gv = 0.5f * v * (1.f + erff(v * 0.70710678118654752f));
        g[i] = gv;
        ss += gv * gv;
    }
#pragma unroll
    for (int o = 16; o > 0; o >>= 1) ss += __shfl_xor_sync(0xffffffffu, ss, o);
    if ((tid & 31) == 0) ws[tid >> 5] = ss;
    __syncthreads();

    float tot = 0.f;
#pragma unroll
    for (int w = 0; w < 8; w++) tot += ws[w];

    const float sc = 32.f * rsqrtf(tot);
    for (int i = tid; i < NTOK; i += 256) {
        float v = g[i] * sc;
        __nv_bfloat16 h, l;
        split_bf16(v, h, l);
        oh[(size_t)row * NTOK + i] = h;
        ol[(size_t)row * NTOK + i] = l;
    }
}

// ---------------- causal flash attention (fp32, f32x2 packed FMA) ---------
// cp.async double-buffered K/V, 8-way split dot, scale folded into q.
__global__ void __launch_bounds__(128) flash_causal(const float* __restrict__ Q,
                                                    const float* __restrict__ K,
                                                    const float* __restrict__ V,
                                                    float* __restrict__ O)
{
    __shared__ float Ks[2][32][HDIM];   // 16 KB
    __shared__ float Vs[2][32][HDIM];   // 16 KB
    __shared__ float Sc[32][128];       // 16 KB  (transposed: conflict-free)

    const int tid  = threadIdx.x;
    const int head = blockIdx.y;
    const int qt   = gridDim.x - 1 - blockIdx.x;   // heavy tiles first
    const int qrow = qt * 128 + tid;

    const float* qp = Q + (size_t)qrow * HID + head * HDIM;
    u64 q2[32], acc2[32];
#pragma unroll
    for (int d = 0; d < HDIM; d += 4) {
        float4 t = *(const float4*)(qp + d);
        q2[d / 2]     = pk2(t.x * 0.125f, t.y * 0.125f);   // fold softmax scale
        q2[d / 2 + 1] = pk2(t.z * 0.125f, t.w * 0.125f);
    }
#pragma unroll
    for (int i = 0; i < 32; i++) acc2[i] = pk2(0.f, 0.f);

    float m = -1e30f, l = 0.f;
    const int nblk = qt * 4 + 4;   // kv blocks of 32 needed (causal)

    auto stage = [&](int blk, int b) {
        const int kb = blk * 32;
#pragma unroll
        for (int i = 0; i < 4; i++) {
            int idx = tid + i * 128;
            int r = idx >> 4, d4 = (idx & 15) << 2;
            cpa16(&Ks[b][r][d4], K + (size_t)(kb + r) * HID + head * HDIM + d4);
            cpa16(&Vs[b][r][d4], V + (size_t)(kb + r) * HID + head * HDIM + d4);
        }
        CPA_COMMIT();
    };

    stage(0, 0);

    for (int blk = 0; blk < nblk; blk++) {
        const int b = blk & 1;
        const int kb = blk * 32;
        if (blk + 1 < nblk) { stage(blk + 1, b ^ 1); CPA_WAIT(1); }
        else                { CPA_WAIT(0); }
        __syncthreads();

        // ---- scores (8-way split accumulators) ----
        float tmax = -1e30f;
        for (int j = 0; j < 32; j++) {
            u64 s8[8];
#pragma unroll
            for (int a = 0; a < 8; a++) s8[a] = pk2(0.f, 0.f);
#pragma unroll
            for (int i = 0; i < 16; i++) {
                float4 kv = *(const float4*)&Ks[b][j][i * 4];
                s8[(2 * i) & 7]     = fma2(q2[2 * i],     pk2(kv.x, kv.y), s8[(2 * i) & 7]);
                s8[(2 * i + 1) & 7] = fma2(q2[2 * i + 1], pk2(kv.z, kv.w), s8[(2 * i + 1) & 7]);
            }
            s8[0] = add2(s8[0], s8[4]); s8[1] = add2(s8[1], s8[5]);
            s8[2] = add2(s8[2], s8[6]); s8[3] = add2(s8[3], s8[7]);
            s8[0] = add2(s8[0], s8[2]); s8[1] = add2(s8[1], s8[3]);
            s8[0] = add2(s8[0], s8[1]);
            float sx, sy; up2(s8[0], sx, sy);
            float s = sx + sy;
            if (kb + j > qrow) s = -1e30f;
            Sc[j][tid] = s;
            tmax = fmaxf(tmax, s);
        }

        if (tmax > -1e29f) {
            float mnew = fmaxf(m, tmax);
            float corr = __expf(m - mnew);
            l *= corr;
            u64 c2 = pk2(corr, corr);
#pragma unroll
            for (int i = 0; i < 32; i++) acc2[i] = mul2(acc2[i], c2);
            for (int j = 0; j < 32; j++) {
                float p = __expf(Sc[j][tid] - mnew);
                l += p;
                u64 p2 = pk2(p, p);
#pragma unroll
                for (int i = 0; i < 16; i++) {
                    float4 vv = *(const float4*)&Vs[b][j][i * 4];
                    acc2[2 * i]     = fma2(p2, pk2(vv.x, vv.y), acc2[2 * i]);
                    acc2[2 * i + 1] = fma2(p2, pk2(vv.z, vv.w), acc2[2 * i + 1]);
                }
            }
            m = mnew;
        }
        __syncthreads();
    }

    const float inv = 1.f / l;
    float* op = O + (size_t)qrow * HID + head * HDIM;
#pragma unroll
    for (int d = 0; d < HDIM; d += 4) {
        float a, bb, c, e;
        up2(acc2[d / 2], a, bb);
        up2(acc2[d / 2 + 1], c, e);
        *(float4*)(op + d) = make_float4(a * inv, bb * inv, c * inv, e * inv);
    }
}

// ---------------------------------------------------------------------------
extern "C" void kernel_launch(void* const* d_in, const int* in_sizes, int n_in,
                              void* d_out, int out_size)
{
    const float* x = (const float*)d_in[0];
    float* out = (float*)d_out;

    float *attnf, *q, *k, *v, *ctx;
    __nv_bfloat16 *attnh, *attnl, *xh, *xl, *ctxh, *ctxl, *wh, *wl;
    cudaGetSymbolAddress((void**)&attnf, g_attnf);
    cudaGetSymbolAddress((void**)&attnh, g_attnh);
    cudaGetSymbolAddress((void**)&attnl, g_attnl);
    cudaGetSymbolAddress((void**)&xh, g_xh);
    cudaGetSymbolAddress((void**)&xl, g_xl);
    cudaGetSymbolAddress((void**)&ctxh, g_ctxh);
    cudaGetSymbolAddress((void**)&ctxl, g_ctxl);
    cudaGetSymbolAddress((void**)&wh, g_wh);
    cudaGetSymbolAddress((void**)&wl, g_wl);
    cudaGetSymbolAddress((void**)&q, g_q);
    cudaGetSymbolAddress((void**)&k, g_k);
    cudaGetSymbolAddress((void**)&v, g_v);
    cudaGetSymbolAddress((void**)&ctx, g_ctx);

    // opt-in dynamic smem (host attribute call; idempotent, capture-safe)
    cudaFuncSetAttribute(tgemm_bf16<true>,
                         cudaFuncAttributeMaxDynamicSharedMemorySize, GEMM_SMEM_BT);
    cudaFuncSetAttribute(tgemm_bf16<false>,
                         cudaFuncAttributeMaxDynamicSharedMemorySize, GEMM_SMEM_BN);

    const int WSZ = NTOK * HID;

    // convert inputs to bf16 hi/lo
    cvt_hilo<<<SEQ * HID / 1024, 256>>>(x, xh, xl);
    W8 w8;
    for (int i = 0; i < 8; i++) w8.src[i] = (const float*)d_in[1 + i];
    cvt_hilo8<<<dim3(WSZ / 1024, 8), 256>>>(w8, wh, wl);

    dim3 gg3(HID / 128, SEQ / 128, 3);
    dim3 gg1(HID / 128, SEQ / 128, 1);
    const size_t AS = (size_t)SEQ * NTOK;

    // ---- QKV pattention, batched over z ----
    GB p1 = {};
    for (int z = 0; z < 3; z++) {
        p1.Ah[z] = xh;  p1.Al[z] = xl;
        p1.Bh[z] = wh + (size_t)(z * 2) * WSZ;
        p1.Bl[z] = wl + (size_t)(z * 2) * WSZ;
        p1.C[z]  = attnf + z * AS;
    }
    tgemm_bf16<true><<<gg3, 256, GEMM_SMEM_BT>>>(p1, SEQ, NTOK, HID);

    gelu_l2norm_cvt<<<3 * SEQ, 256>>>(attnf, attnh, attnl);

    GB p2 = {};
    float* qkv[3] = {q, k, v};
    for (int z = 0; z < 3; z++) {
        p2.Ah[z] = attnh + z * AS;  p2.Al[z] = attnl + z * AS;
        p2.Bh[z] = wh + (size_t)(z * 2 + 1) * WSZ;
        p2.Bl[z] = wl + (size_t)(z * 2 + 1) * WSZ;
        p2.C[z]  = qkv[z];
    }
    tgemm_bf16<false><<<gg3, 256, GEMM_SMEM_BN>>>(p2, SEQ, HID, NTOK);

    // ---- causal attention ----
    flash_causal<<<dim3(SEQ / 128, NHEAD), 128>>>(q, k, v, ctx);

    // ---- output projection pattention ----
    cvt_hilo<<<SEQ * HID / 1024, 256>>>(ctx, ctxh, ctxl);

    GB p3 = {};
    p3.Ah[0] = ctxh; p3.Al[0] = ctxl;
    p3.Bh[0] = wh + (size_t)6 * WSZ;  p3.Bl[0] = wl + (size_t)6 * WSZ;
    p3.C[0]  = attnf;
    tgemm_bf16<true><<<gg1, 256, GEMM_SMEM_BT>>>(p3, SEQ, NTOK, HID);

    gelu_l2norm_cvt<<<SEQ, 256>>>(attnf, attnh, attnl);

    GB p4 = {};
    p4.Ah[0] = attnh; p4.Al[0] = attnl;
    p4.Bh[0] = wh + (size_t)7 * WSZ;  p4.Bl[0] = wl + (size_t)7 * WSZ;
    p4.C[0]  = out;
    tgemm_bf16<false><<<gg1, 256, GEMM_SMEM_BN>>>(p4, SEQ, HID, NTOK);
}

// round 5
// speedup vs baseline: 2.5642x; 1.3303x over previous
#include <cuda_runtime.h>
#include <cuda_bf16.h>
#include <mma.h>
#include <math.h>

using namespace nvcuda;

#define SEQ   2048
#define HID   1024
#define NTOK  1024
#define NHEAD 16
#define HDIM  64

typedef unsigned long long u64;
typedef __nv_bfloat16 bf16;

// ---------------- scratch (device globals; no runtime allocation) ----------
__device__ float g_attnf[3 * SEQ * NTOK];
__device__ bf16 g_attnh[3 * SEQ * NTOK];
__device__ bf16 g_attnl[3 * SEQ * NTOK];
__device__ bf16 g_xh[SEQ * HID], g_xl[SEQ * HID];
__device__ bf16 g_ctxh[SEQ * HID], g_ctxl[SEQ * HID];
__device__ bf16 g_wh[8][NTOK * HID];   // qk,qv,kk,kv,vk,vv,pk,pv
__device__ bf16 g_wl[8][NTOK * HID];
__device__ float g_q[SEQ * HID];
__device__ float g_k[SEQ * HID];
__device__ float g_v[SEQ * HID];
__device__ bf16 g_qkvh[3 * SEQ * HID];  // q(scaled),k,v hi
__device__ bf16 g_qkvl[3 * SEQ * HID];  // q(scaled),k,v lo

// ---------------- small helpers -------------------------------------------
__device__ __forceinline__ unsigned short b2u(bf16 h) {
    return *reinterpret_cast<unsigned short*>(&h);
}
__device__ __forceinline__ unsigned pb2(bf16 a, bf16 b) {
    return (unsigned)b2u(a) | ((unsigned)b2u(b) << 16);
}
__device__ __forceinline__ void split_bf16(float x, bf16& h, bf16& l) {
    h = __float2bfloat16_rn(x);
    l = __float2bfloat16_rn(x - __bfloat162float(h));
}
__device__ __forceinline__ void cpa16(void* smem, const void* gmem) {
    unsigned s = (unsigned)__cvta_generic_to_shared(smem);
    asm volatile("cp.async.cg.shared.global [%0], [%1], 16;" :: "r"(s), "l"(gmem));
}
#define CPA_COMMIT() asm volatile("cp.async.commit_group;")
#define CPA_WAIT(n)  asm volatile("cp.async.wait_group %0;" :: "n"(n))

// ---------------- fp32 -> bf16 hi/lo conversion ---------------------------
__global__ void __launch_bounds__(256) cvt_hilo(const float* __restrict__ in,
                                                bf16* __restrict__ hi,
                                                bf16* __restrict__ lo)
{
    int i = (blockIdx.x * 256 + threadIdx.x) * 4;
    float4 v = *(const float4*)(in + i);
    bf16 h0, h1, h2, h3, l0, l1, l2, l3;
    split_bf16(v.x, h0, l0); split_bf16(v.y, h1, l1);
    split_bf16(v.z, h2, l2); split_bf16(v.w, h3, l3);
    uint2 H; H.x = pb2(h0, h1); H.y = pb2(h2, h3);
    uint2 L; L.x = pb2(l0, l1); L.y = pb2(l2, l3);
    *(uint2*)(hi + i) = H;
    *(uint2*)(lo + i) = L;
}

struct W8 { const float* src[8]; };

__global__ void __launch_bounds__(256) cvt_hilo8(W8 s,
                                                 bf16* __restrict__ hi,
                                                 bf16* __restrict__ lo)
{
    const size_t WSZ = (size_t)NTOK * HID;
    int z = blockIdx.y;
    int i = (blockIdx.x * 256 + threadIdx.x) * 4;
    float4 v = *(const float4*)(s.src[z] + i);
    bf16 h0, h1, h2, h3, l0, l1, l2, l3;
    split_bf16(v.x, h0, l0); split_bf16(v.y, h1, l1);
    split_bf16(v.z, h2, l2); split_bf16(v.w, h3, l3);
    uint2 H; H.x = pb2(h0, h1); H.y = pb2(h2, h3);
    uint2 L; L.x = pb2(l0, l1); L.y = pb2(l2, l3);
    *(uint2*)(hi + z * WSZ + i) = H;
    *(uint2*)(lo + z * WSZ + i) = L;
}

// q/k/v fp32 -> hi/lo bf16 (q gets softmax scale folded in)
__global__ void __launch_bounds__(256) cvt_qkv(const float* __restrict__ q,
                                               const float* __restrict__ k,
                                               const float* __restrict__ v,
                                               bf16* __restrict__ hi,
                                               bf16* __restrict__ lo)
{
    const size_t SZ = (size_t)SEQ * HID;
    int z = blockIdx.y;
    const float* src = z == 0 ? q : (z == 1 ? k : v);
    const float sc = z == 0 ? 0.125f : 1.f;
    int i = (blockIdx.x * 256 + threadIdx.x) * 4;
    float4 t = *(const float4*)(src + i);
    bf16 h0, h1, h2, h3, l0, l1, l2, l3;
    split_bf16(t.x * sc, h0, l0); split_bf16(t.y * sc, h1, l1);
    split_bf16(t.z * sc, h2, l2); split_bf16(t.w * sc, h3, l3);
    uint2 H; H.x = pb2(h0, h1); H.y = pb2(h2, h3);
    uint2 L; L.x = pb2(l0, l1); L.y = pb2(l2, l3);
    *(uint2*)(hi + z * SZ + i) = H;
    *(uint2*)(lo + z * SZ + i) = L;
}

// ---------------- tensor GEMM (bf16 hi/lo, 3 compensated terms) -----------
struct GB {
    const bf16 *Ah[3], *Al[3], *Bh[3], *Bl[3];
    float* C[3];
};

template <bool BT>
__global__ void __launch_bounds__(256, 2) tgemm_bf16(GB p, int M, int N, int K)
{
    constexpr int ASZ = 128 * 40;
    constexpr int BSZ = BT ? (128 * 40) : (32 * 136);

    extern __shared__ bf16 dyn[];
    bf16* As_h = dyn;
    bf16* As_l = dyn + 2 * ASZ;
    bf16* Bs_h = dyn + 4 * ASZ;
    bf16* Bs_l = dyn + 4 * ASZ + 2 * BSZ;

    const int z = blockIdx.z;
    const bf16* __restrict__ Ah = p.Ah[z];
    const bf16* __restrict__ Al = p.Al[z];
    const bf16* __restrict__ Bh = p.Bh[z];
    const bf16* __restrict__ Bl = p.Bl[z];
    float* __restrict__ C = p.C[z];

    const int tid = threadIdx.x;
    const int bx = blockIdx.x;
    const int by = blockIdx.y;
    const int wid = tid >> 5;
    const int wm = wid & 3;
    const int wn = wid >> 2;

    wmma::fragment<wmma::accumulator, 16, 16, 16, float> cf[2][4];
#pragma unroll
    for (int mi = 0; mi < 2; mi++)
#pragma unroll
        for (int ni = 0; ni < 4; ni++) wmma::fill_fragment(cf[mi][ni], 0.f);

    int arow[2], akq[2], bkr[2], bnq[2];
#pragma unroll
    for (int i = 0; i < 2; i++) {
        int c = tid + i * 256;
        arow[i] = c >> 2;  akq[i] = (c & 3) * 8;
        if (BT) { bkr[i] = c >> 2;  bnq[i] = (c & 3) * 8; }
        else    { bkr[i] = c >> 4;  bnq[i] = (c & 15) * 8; }
    }

    const int T = K / 32;

    auto stage = [&](int t, int b) {
        const int kt = t * 32;
#pragma unroll
        for (int i = 0; i < 2; i++) {
            cpa16(As_h + b * ASZ + arow[i] * 40 + akq[i],
                  Ah + (size_t)(by * 128 + arow[i]) * K + kt + akq[i]);
            cpa16(As_l + b * ASZ + arow[i] * 40 + akq[i],
                  Al + (size_t)(by * 128 + arow[i]) * K + kt + akq[i]);
            if (BT) {
                cpa16(Bs_h + b * BSZ + bkr[i] * 40 + bnq[i],
                      Bh + (size_t)(bx * 128 + bkr[i]) * K + kt + bnq[i]);
                cpa16(Bs_l + b * BSZ + bkr[i] * 40 + bnq[i],
                      Bl + (size_t)(bx * 128 + bkr[i]) * K + kt + bnq[i]);
            } else {
                cpa16(Bs_h + b * BSZ + bkr[i] * 136 + bnq[i],
                      Bh + (size_t)(kt + bkr[i]) * N + bx * 128 + bnq[i]);
                cpa16(Bs_l + b * BSZ + bkr[i] * 136 + bnq[i],
                      Bl + (size_t)(kt + bkr[i]) * N + bx * 128 + bnq[i]);
            }
        }
        CPA_COMMIT();
    };

    stage(0, 0);

    for (int t = 0; t < T; t++) {
        const int b = t & 1;
        if (t + 1 < T) { stage(t + 1, b ^ 1); CPA_WAIT(1); }
        else           { CPA_WAIT(0); }
        __syncthreads();

        const bf16* ah_p = As_h + b * ASZ;
        const bf16* al_p = As_l + b * ASZ;
        const bf16* bh_p = Bs_h + b * BSZ;
        const bf16* bl_p = Bs_l + b * BSZ;

#pragma unroll
        for (int kk = 0; kk < 2; kk++) {
            wmma::fragment<wmma::matrix_a, 16, 16, 16, bf16,
                           wmma::row_major> ah[2], al[2];
#pragma unroll
            for (int mi = 0; mi < 2; mi++) {
                wmma::load_matrix_sync(ah[mi], ah_p + (wm * 32 + mi * 16) * 40 + kk * 16, 40);
                wmma::load_matrix_sync(al[mi], al_p + (wm * 32 + mi * 16) * 40 + kk * 16, 40);
            }
            if (BT) {
                wmma::fragment<wmma::matrix_b, 16, 16, 16, bf16,
                               wmma::col_major> bh[4], bl[4];
#pragma unroll
                for (int ni = 0; ni < 4; ni++) {
                    wmma::load_matrix_sync(bh[ni], bh_p + (wn * 64 + ni * 16) * 40 + kk * 16, 40);
                    wmma::load_matrix_sync(bl[ni], bl_p + (wn * 64 + ni * 16) * 40 + kk * 16, 40);
                }
#pragma unroll
                for (int mi = 0; mi < 2; mi++)
#pragma unroll
                    for (int ni = 0; ni < 4; ni++) {
                        wmma::mma_sync(cf[mi][ni], ah[mi], bh[ni], cf[mi][ni]);
                        wmma::mma_sync(cf[mi][ni], al[mi], bh[ni], cf[mi][ni]);
                        wmma::mma_sync(cf[mi][ni], ah[mi], bl[ni], cf[mi][ni]);
                    }
            } else {
                wmma::fragment<wmma::matrix_b, 16, 16, 16, bf16,
                               wmma::row_major> bh[4], bl[4];
#pragma unroll
                for (int ni = 0; ni < 4; ni++) {
                    wmma::load_matrix_sync(bh[ni], bh_p + kk * 16 * 136 + wn * 64 + ni * 16, 136);
                    wmma::load_matrix_sync(bl[ni], bl_p + kk * 16 * 136 + wn * 64 + ni * 16, 136);
                }
#pragma unroll
                for (int mi = 0; mi < 2; mi++)
#pragma unroll
                    for (int ni = 0; ni < 4; ni++) {
                        wmma::mma_sync(cf[mi][ni], ah[mi], bh[ni], cf[mi][ni]);
                        wmma::mma_sync(cf[mi][ni], al[mi], bh[ni], cf[mi][ni]);
                        wmma::mma_sync(cf[mi][ni], ah[mi], bl[ni], cf[mi][ni]);
                    }
            }
        }
        __syncthreads();
    }

#pragma unroll
    for (int mi = 0; mi < 2; mi++)
#pragma unroll
        for (int ni = 0; ni < 4; ni++) {
            float* Cp = C + (size_t)(by * 128 + wm * 32 + mi * 16) * N
                          + bx * 128 + wn * 64 + ni * 16;
            wmma::store_matrix_sync(Cp, cf[mi][ni], N, wmma::mem_row_major);
        }
}

#define GEMM_SMEM_BT   ((4 * 128 * 40 + 4 * 128 * 40) * 2)
#define GEMM_SMEM_BN   ((4 * 128 * 40 + 4 * 32 * 136) * 2)

// ---------------- gelu + L2-norm, writing bf16 hi/lo ----------------------
__global__ void __launch_bounds__(256) gelu_l2norm_cvt(const float* __restrict__ in,
                                                       bf16* __restrict__ oh,
                                                       bf16* __restrict__ ol)
{
    const int row = blockIdx.x;
    const int tid = threadIdx.x;
    __shared__ float g[NTOK];
    __shared__ float ws[8];

    const float* rp = in + (size_t)row * NTOK;

    float ss = 0.f;
    for (int i = tid; i < NTOK; i += 256) {
        float v = rp[i];
        float gv = 0.5f * v * (1.f + erff(v * 0.70710678118654752f));
        g[i] = gv;
        ss += gv * gv;
    }
#pragma unroll
    for (int o = 16; o > 0; o >>= 1) ss += __shfl_xor_sync(0xffffffffu, ss, o);
    if ((tid & 31) == 0) ws[tid >> 5] = ss;
    __syncthreads();

    float tot = 0.f;
#pragma unroll
    for (int w = 0; w < 8; w++) tot += ws[w];

    const float sc = 32.f * rsqrtf(tot);
    for (int i = tid; i < NTOK; i += 256) {
        float v = g[i] * sc;
        bf16 h, l;
        split_bf16(v, h, l);
        oh[(size_t)row * NTOK + i] = h;
        ol[(size_t)row * NTOK + i] = l;
    }
}

// ---------------- tensor-core causal flash attention ----------------------
// CTA = (head, 128-q-tile). 8 warps, 256 threads.
// QK^T and P*V via wmma bf16 with 3-term hi/lo compensation.
// Softmax scale pre-folded into Q. KV tiles of 64, cp.async double buffered.
#define FPAD 72   // bf16 row stride (mult of 8)
#define SPAD 68   // fp32 row stride (mult of 4)

__global__ void __launch_bounds__(256) flash_tc(const bf16* __restrict__ qkvh,
                                                const bf16* __restrict__ qkvl,
                                                bf16* __restrict__ ctxh,
                                                bf16* __restrict__ ctxl)
{
    const size_t SZ = (size_t)SEQ * HID;
    const int tid  = threadIdx.x;
    const int wid  = tid >> 5;
    const int head = blockIdx.y;
    const int qt   = gridDim.x - 1 - blockIdx.x;   // heavy tiles first
    const int hc   = head * HDIM;

    extern __shared__ char dynb[];
    bf16*  Qh  = (bf16*)dynb;                       // [128][72]
    bf16*  Ql  = Qh + 128 * FPAD;
    bf16*  KVs = Ql + 128 * FPAD;                   // [2 buf][4 arr][64*72]
    float* S   = (float*)(KVs + 2 * 4 * 64 * FPAD); // [128][68] scores / PVtmp
    float* O   = S + 128 * SPAD;                    // [128][68]
    bf16*  Ph  = (bf16*)(O + 128 * SPAD);           // [128][72]
    bf16*  Pl  = Ph + 128 * FPAD;
    float* sm_m = (float*)(Pl + 128 * FPAD);
    float* sm_l = sm_m + 128;
    float* sm_c = sm_l + 128;

    // ---- init ----
    for (int i = tid; i < 128 * SPAD; i += 256) O[i] = 0.f;
    if (tid < 128) { sm_m[tid] = -1e30f; sm_l[tid] = 0.f; }

    // ---- stage Q (hi/lo) ----
    for (int i = tid; i < 1024; i += 256) {
        int r = i >> 3, c8 = (i & 7) * 8;
        size_t g = (size_t)(qt * 128 + r) * HID + hc + c8;
        cpa16(Qh + r * FPAD + c8, qkvh + g);
        cpa16(Ql + r * FPAD + c8, qkvl + g);
    }
    CPA_COMMIT();

    auto stageKV = [&](int step, int buf) {
        const int kb = step * 64;
        bf16* base = KVs + buf * (4 * 64 * FPAD);
        for (int i = tid; i < 512; i += 256) {
            int r = i >> 3, c8 = (i & 7) * 8;
            size_t g = (size_t)(kb + r) * HID + hc + c8;
            cpa16(base + 0 * 64 * FPAD + r * FPAD + c8, qkvh + SZ + g);      // Kh
            cpa16(base + 1 * 64 * FPAD + r * FPAD + c8, qkvl + SZ + g);      // Kl
            cpa16(base + 2 * 64 * FPAD + r * FPAD + c8, qkvh + 2 * SZ + g);  // Vh
            cpa16(base + 3 * 64 * FPAD + r * FPAD + c8, qkvl + 2 * SZ + g);  // Vl
        }
        CPA_COMMIT();
    };

    const int nsteps = 2 * qt + 2;
    stageKV(0, 0);
    CPA_WAIT(0);
    __syncthreads();

    const int wq = wid * 16;   // warp's q-row base within tile

    for (int step = 0; step < nsteps; step++) {
        const int buf = step & 1;
        const int kb  = step * 64;
        if (step + 1 < nsteps) { stageKV(step + 1, buf ^ 1); CPA_WAIT(1); }
        else                   { CPA_WAIT(0); }
        __syncthreads();

        const bf16* kh = KVs + buf * (4 * 64 * FPAD);
        const bf16* kl = kh + 64 * FPAD;
        const bf16* vh = kh + 2 * 64 * FPAD;
        const bf16* vl = kh + 3 * 64 * FPAD;

        // ---- QK^T: S[128q][64kv] ----
        {
            wmma::fragment<wmma::matrix_a, 16, 16, 16, bf16, wmma::row_major> ah[4], al[4];
#pragma unroll
            for (int ks = 0; ks < 4; ks++) {
                wmma::load_matrix_sync(ah[ks], Qh + wq * FPAD + ks * 16, FPAD);
                wmma::load_matrix_sync(al[ks], Ql + wq * FPAD + ks * 16, FPAD);
            }
#pragma unroll
            for (int nf = 0; nf < 4; nf++) {
                wmma::fragment<wmma::accumulator, 16, 16, 16, float> acc;
                wmma::fill_fragment(acc, 0.f);
#pragma unroll
                for (int ks = 0; ks < 4; ks++) {
                    wmma::fragment<wmma::matrix_b, 16, 16, 16, bf16, wmma::col_major> bh, bl;
                    wmma::load_matrix_sync(bh, kh + nf * 16 * FPAD + ks * 16, FPAD);
                    wmma::load_matrix_sync(bl, kl + nf * 16 * FPAD + ks * 16, FPAD);
                    wmma::mma_sync(acc, ah[ks], bh, acc);
                    wmma::mma_sync(acc, al[ks], bh, acc);
                    wmma::mma_sync(acc, ah[ks], bl, acc);
                }
                wmma::store_matrix_sync(S + wq * SPAD + nf * 16, acc, SPAD,
                                        wmma::mem_row_major);
            }
        }
        __syncthreads();

        // ---- online softmax (one thread per q row) ----
        if (tid < 128) {
            const int qrow = qt * 128 + tid;
            int jmax = qrow - kb + 1;
            if (jmax > 64) jmax = 64;
            unsigned* ph = (unsigned*)(Ph + tid * FPAD);
            unsigned* pl = (unsigned*)(Pl + tid * FPAD);
            if (jmax <= 0) {
                sm_c[tid] = 1.f;
#pragma unroll
                for (int j = 0; j < 32; j++) { ph[j] = 0u; pl[j] = 0u; }
            } else {
                const float* Srow = S + tid * SPAD;
                float m = sm_m[tid];
                float tmax = -1e30f;
                for (int j = 0; j < jmax; j++) tmax = fmaxf(tmax, Srow[j]);
                float mnew = fmaxf(m, tmax);
                float corr = __expf(m - mnew);
                float suml = 0.f;
                for (int j2 = 0; j2 < 32; j2++) {
                    int ja = 2 * j2, jb = 2 * j2 + 1;
                    float pa = (ja < jmax) ? __expf(Srow[ja] - mnew) : 0.f;
                    float pb = (jb < jmax) ? __expf(Srow[jb] - mnew) : 0.f;
                    suml += pa + pb;
                    bf16 ha, la, hb, lb;
                    split_bf16(pa, ha, la); split_bf16(pb, hb, lb);
                    ph[j2] = pb2(ha, hb);
                    pl[j2] = pb2(la, lb);
                }
                sm_l[tid] = sm_l[tid] * corr + suml;
                sm_m[tid] = mnew;
                sm_c[tid] = corr;
            }
        }
        __syncthreads();

        // ---- P*V: PVtmp[128q][64d] (reuse S) ----
        {
            wmma::fragment<wmma::matrix_a, 16, 16, 16, bf16, wmma::row_major> pah[4], pal[4];
#pragma unroll
            for (int ks = 0; ks < 4; ks++) {
                wmma::load_matrix_sync(pah[ks], Ph + wq * FPAD + ks * 16, FPAD);
                wmma::load_matrix_sync(pal[ks], Pl + wq * FPAD + ks * 16, FPAD);
            }
#pragma unroll
            for (int nf = 0; nf < 4; nf++) {
                wmma::fragment<wmma::accumulator, 16, 16, 16, float> acc;
                wmma::fill_fragment(acc, 0.f);
#pragma unroll
                for (int ks = 0; ks < 4; ks++) {
                    wmma::fragment<wmma::matrix_b, 16, 16, 16, bf16, wmma::row_major> bh, bl;
                    wmma::load_matrix_sync(bh, vh + ks * 16 * FPAD + nf * 16, FPAD);
                    wmma::load_matrix_sync(bl, vl + ks * 16 * FPAD + nf * 16, FPAD);
                    wmma::mma_sync(acc, pah[ks], bh, acc);
                    wmma::mma_sync(acc, pal[ks], bh, acc);
                    wmma::mma_sync(acc, pah[ks], bl, acc);
                }
                wmma::store_matrix_sync(S + wq * SPAD + nf * 16, acc, SPAD,
                                        wmma::mem_row_major);
            }
        }
        __syncthreads();

        // ---- O = O*corr + PV ----
#pragma unroll
        for (int t = 0; t < 32; t++) {
            int idx = tid + t * 256;
            int r = idx >> 6, c = idx & 63;
            O[r * SPAD + c] = O[r * SPAD + c] * sm_c[r] + S[r * SPAD + c];
        }
        __syncthreads();
    }

    // ---- epilogue: O/l -> ctx hi/lo bf16 ----
#pragma unroll
    for (int t = 0; t < 32; t++) {
        int idx = tid + t * 256;
        int r = idx >> 6, c = idx & 63;
        float val = O[r * SPAD + c] / sm_l[r];
        bf16 h, l;
        split_bf16(val, h, l);
        size_t g = (size_t)(qt * 128 + r) * HID + hc + c;
        ctxh[g] = h;
        ctxl[g] = l;
    }
}

#define FLASH_SMEM (2*128*FPAD*2 + 2*4*64*FPAD*2 + 2*128*SPAD*4 + 2*128*FPAD*2 + 3*128*4 + 128)

// ---------------------------------------------------------------------------
extern "C" void kernel_launch(void* const* d_in, const int* in_sizes, int n_in,
                              void* d_out, int out_size)
{
    const float* x = (const float*)d_in[0];
    float* out = (float*)d_out;

    float *attnf, *q, *k, *v;
    bf16 *attnh, *attnl, *xh, *xl, *ctxh, *ctxl, *wh, *wl, *qkvh, *qkvl;
    cudaGetSymbolAddress((void**)&attnf, g_attnf);
    cudaGetSymbolAddress((void**)&attnh, g_attnh);
    cudaGetSymbolAddress((void**)&attnl, g_attnl);
    cudaGetSymbolAddress((void**)&xh, g_xh);
    cudaGetSymbolAddress((void**)&xl, g_xl);
    cudaGetSymbolAddress((void**)&ctxh, g_ctxh);
    cudaGetSymbolAddress((void**)&ctxl, g_ctxl);
    cudaGetSymbolAddress((void**)&wh, g_wh);
    cudaGetSymbolAddress((void**)&wl, g_wl);
    cudaGetSymbolAddress((void**)&q, g_q);
    cudaGetSymbolAddress((void**)&k, g_k);
    cudaGetSymbolAddress((void**)&v, g_v);
    cudaGetSymbolAddress((void**)&qkvh, g_qkvh);
    cudaGetSymbolAddress((void**)&qkvl, g_qkvl);

    cudaFuncSetAttribute(tgemm_bf16<true>,
                         cudaFuncAttributeMaxDynamicSharedMemorySize, GEMM_SMEM_BT);
    cudaFuncSetAttribute(tgemm_bf16<false>,
                         cudaFuncAttributeMaxDynamicSharedMemorySize, GEMM_SMEM_BN);
    cudaFuncSetAttribute(flash_tc,
                         cudaFuncAttributeMaxDynamicSharedMemorySize, FLASH_SMEM);

    const int WSZ = NTOK * HID;

    cvt_hilo<<<SEQ * HID / 1024, 256>>>(x, xh, xl);
    W8 w8;
    for (int i = 0; i < 8; i++) w8.src[i] = (const float*)d_in[1 + i];
    cvt_hilo8<<<dim3(WSZ / 1024, 8), 256>>>(w8, wh, wl);

    dim3 gg3(HID / 128, SEQ / 128, 3);
    dim3 gg1(HID / 128, SEQ / 128, 1);
    const size_t AS = (size_t)SEQ * NTOK;

    // ---- QKV pattention (batched over z) ----
    GB p1 = {};
    for (int z = 0; z < 3; z++) {
        p1.Ah[z] = xh;  p1.Al[z] = xl;
        p1.Bh[z] = wh + (size_t)(z * 2) * WSZ;
        p1.Bl[z] = wl + (size_t)(z * 2) * WSZ;
        p1.C[z]  = attnf + z * AS;
    }
    tgemm_bf16<true><<<gg3, 256, GEMM_SMEM_BT>>>(p1, SEQ, NTOK, HID);

    gelu_l2norm_cvt<<<3 * SEQ, 256>>>(attnf, attnh, attnl);

    GB p2 = {};
    float* qkv[3] = {q, k, v};
    for (int z = 0; z < 3; z++) {
        p2.Ah[z] = attnh + z * AS;  p2.Al[z] = attnl + z * AS;
        p2.Bh[z] = wh + (size_t)(z * 2 + 1) * WSZ;
        p2.Bl[z] = wl + (size_t)(z * 2 + 1) * WSZ;
        p2.C[z]  = qkv[z];
    }
    tgemm_bf16<false><<<gg3, 256, GEMM_SMEM_BN>>>(p2, SEQ, HID, NTOK);

    // ---- split q/k/v to bf16 hi/lo (q scaled by 1/8) ----
    cvt_qkv<<<dim3(SEQ * HID / 1024, 3), 256>>>(q, k, v, qkvh, qkvl);

    // ---- tensor-core causal attention -> ctx hi/lo ----
    flash_tc<<<dim3(SEQ / 128, NHEAD), 256, FLASH_SMEM>>>(qkvh, qkvl, ctxh, ctxl);

    // ---- output projection pattention ----
    GB p3 = {};
    p3.Ah[0] = ctxh; p3.Al[0] = ctxl;
    p3.Bh[0] = wh + (size_t)6 * WSZ;  p3.Bl[0] = wl + (size_t)6 * WSZ;
    p3.C[0]  = attnf;
    tgemm_bf16<true><<<gg1, 256, GEMM_SMEM_BT>>>(p3, SEQ, NTOK, HID);

    gelu_l2norm_cvt<<<SEQ, 256>>>(attnf, attnh, attnl);

    GB p4 = {};
    p4.Ah[0] = attnh; p4.Al[0] = attnl;
    p4.Bh[0] = wh + (size_t)7 * WSZ;  p4.Bl[0] = wl + (size_t)7 * WSZ;
    p4.C[0]  = out;
    tgemm_bf16<false><<<gg1, 256, GEMM_SMEM_BN>>>(p4, SEQ, HID, NTOK);
}

// round 8
// speedup vs baseline: 2.5751x; 1.0043x over previous
#include <cuda_runtime.h>
#include <cuda_bf16.h>
#include <mma.h>
#include <math.h>
#include <cstdint>

using namespace nvcuda;

#define SEQ   2048
#define HID   1024
#define NTOK  1024
#define NHEAD 16
#define HDIM  64

typedef __nv_bfloat16 bf16;

// ---------------- scratch (device globals; no runtime allocation) ----------
__device__ float g_attnf[3 * SEQ * NTOK];
__device__ bf16 g_attnh[3 * SEQ * NTOK];
__device__ bf16 g_attnl[3 * SEQ * NTOK];
__device__ bf16 g_xh[SEQ * HID], g_xl[SEQ * HID];
__device__ bf16 g_ctxh[SEQ * HID], g_ctxl[SEQ * HID];
__device__ bf16 g_wh[8][NTOK * HID];   // qk,qv,kk,kv,vk,vv,pk,pv
__device__ bf16 g_wl[8][NTOK * HID];
__device__ bf16 g_qkvh[3 * SEQ * HID]; // q(scaled),k,v hi
__device__ bf16 g_qkvl[3 * SEQ * HID];

// ---------------- small helpers -------------------------------------------
__device__ __forceinline__ unsigned short b2u(bf16 h) {
    return *reinterpret_cast<unsigned short*>(&h);
}
__device__ __forceinline__ unsigned pb2(bf16 a, bf16 b) {
    return (unsigned)b2u(a) | ((unsigned)b2u(b) << 16);
}
__device__ __forceinline__ void split_bf16(float x, bf16& h, bf16& l) {
    h = __float2bfloat16_rn(x);
    l = __float2bfloat16_rn(x - __bfloat162float(h));
}
__device__ __forceinline__ void cpa16(void* smem, const void* gmem) {
    unsigned s = (unsigned)__cvta_generic_to_shared(smem);
    asm volatile("cp.async.cg.shared.global [%0], [%1], 16;" :: "r"(s), "l"(gmem));
}
#define CPA_COMMIT() asm volatile("cp.async.commit_group;")
#define CPA_WAIT(n)  asm volatile("cp.async.wait_group %0;" :: "n"(n))

// ---------------- conversions ----------------------------------------------
__global__ void __launch_bounds__(256) cvt_hilo(const float* __restrict__ in,
                                                bf16* __restrict__ hi,
                                                bf16* __restrict__ lo)
{
    int i = (blockIdx.x * 256 + threadIdx.x) * 4;
    float4 v = *(const float4*)(in + i);
    bf16 h0, h1, h2, h3, l0, l1, l2, l3;
    split_bf16(v.x, h0, l0); split_bf16(v.y, h1, l1);
    split_bf16(v.z, h2, l2); split_bf16(v.w, h3, l3);
    uint2 H; H.x = pb2(h0, h1); H.y = pb2(h2, h3);
    uint2 L; L.x = pb2(l0, l1); L.y = pb2(l2, l3);
    *(uint2*)(hi + i) = H;
    *(uint2*)(lo + i) = L;
}

struct W8 { const float* src[8]; };

__global__ void __launch_bounds__(256) cvt_hilo8(W8 s,
                                                 bf16* __restrict__ hi,
                                                 bf16* __restrict__ lo)
{
    const size_t WSZ = (size_t)NTOK * HID;
    int z = blockIdx.y;
    int i = (blockIdx.x * 256 + threadIdx.x) * 4;
    float4 v = *(const float4*)(s.src[z] + i);
    bf16 h0, h1, h2, h3, l0, l1, l2, l3;
    split_bf16(v.x, h0, l0); split_bf16(v.y, h1, l1);
    split_bf16(v.z, h2, l2); split_bf16(v.w, h3, l3);
    uint2 H; H.x = pb2(h0, h1); H.y = pb2(h2, h3);
    uint2 L; L.x = pb2(l0, l1); L.y = pb2(l2, l3);
    *(uint2*)(hi + z * WSZ + i) = H;
    *(uint2*)(lo + z * WSZ + i) = L;
}

// ---------------- tensor GEMM (bf16 hi/lo, 3 compensated terms) -----------
//  BT=true : B is [N,K] row-major (C = A*B^T)
//  BT=false: B is [K,N] row-major (C = A*B)
//  HILO=true: write scaled bf16 hi/lo instead of fp32 C.
//  64x128 block tile, BK=32, 128 threads (4 warps 2x2, warp tile 32x64).
struct GB {
    const bf16 *Ah[3], *Al[3], *Bh[3], *Bl[3];
    float* C[3];
    bf16 *Oh[3], *Ol[3];
    float scale[3];
};

#define ASZ 2560                       // 64*40
#define BSZ_BT 5120                    // 128*40
#define BSZ_NBT 4352                   // 32*136
#define GEMM_SMEM_BT  ((2 * ASZ + 2 * BSZ_BT) * 2 * 2)    // 61440
#define GEMM_SMEM_BN  ((2 * ASZ + 2 * BSZ_NBT) * 2 * 2)   // 55296

template <bool BT, bool HILO>
__global__ void __launch_bounds__(128, 3) tgemm_bf16(GB p, int M, int N, int K)
{
    constexpr int BSZ = BT ? BSZ_BT : BSZ_NBT;

    extern __shared__ bf16 dyn[];
    bf16* As_h = dyn;                       // [2][ASZ]
    bf16* As_l = dyn + 2 * ASZ;
    bf16* Bs_h = dyn + 4 * ASZ;             // [2][BSZ]
    bf16* Bs_l = dyn + 4 * ASZ + 2 * BSZ;

    const int z = blockIdx.z;
    const bf16* __restrict__ Ah = p.Ah[z];
    const bf16* __restrict__ Al = p.Al[z];
    const bf16* __restrict__ Bh = p.Bh[z];
    const bf16* __restrict__ Bl = p.Bl[z];

    const int tid = threadIdx.x;
    const int bx = blockIdx.x;   // N tile (128 wide)
    const int by = blockIdx.y;   // M tile (64 tall)
    const int wid = tid >> 5;
    const int wm = wid >> 1;     // 0..1
    const int wn = wid & 1;      // 0..1

    wmma::fragment<wmma::accumulator, 16, 16, 16, float> cf[2][4];
#pragma unroll
    for (int mi = 0; mi < 2; mi++)
#pragma unroll
        for (int ni = 0; ni < 4; ni++) wmma::fill_fragment(cf[mi][ni], 0.f);

    const int T = K / 32;

    auto stage = [&](int t, int b) {
        const int kt = t * 32;
        // A: 64 rows x 32 k = 256 16B-chunks, 2 per thread
#pragma unroll
        for (int i = 0; i < 2; i++) {
            int c = tid + i * 128;
            int row = c >> 2, kq = (c & 3) * 8;
            const bf16* ga = Ah + (size_t)(by * 64 + row) * K + kt + kq;
            const bf16* gl = Al + (size_t)(by * 64 + row) * K + kt + kq;
            cpa16(As_h + b * ASZ + row * 40 + kq, ga);
            cpa16(As_l + b * ASZ + row * 40 + kq, gl);
        }
        // B: 512 chunks, 4 per thread
#pragma unroll
        for (int i = 0; i < 4; i++) {
            int c = tid + i * 128;
            if (BT) {
                int row = c >> 2, kq = (c & 3) * 8;
                const bf16* gh = Bh + (size_t)(bx * 128 + row) * K + kt + kq;
                const bf16* gl = Bl + (size_t)(bx * 128 + row) * K + kt + kq;
                cpa16(Bs_h + b * BSZ + row * 40 + kq, gh);
                cpa16(Bs_l + b * BSZ + row * 40 + kq, gl);
            } else {
                int kr = c >> 4, nq = (c & 15) * 8;
                const bf16* gh = Bh + (size_t)(kt + kr) * N + bx * 128 + nq;
                const bf16* gl = Bl + (size_t)(kt + kr) * N + bx * 128 + nq;
                cpa16(Bs_h + b * BSZ + kr * 136 + nq, gh);
                cpa16(Bs_l + b * BSZ + kr * 136 + nq, gl);
            }
        }
        CPA_COMMIT();
    };

    stage(0, 0);

    for (int t = 0; t < T; t++) {
        const int b = t & 1;
        if (t + 1 < T) { stage(t + 1, b ^ 1); CPA_WAIT(1); }
        else           { CPA_WAIT(0); }
        __syncthreads();

        const bf16* ah_p = As_h + b * ASZ;
        const bf16* al_p = As_l + b * ASZ;
        const bf16* bh_p = Bs_h + b * BSZ;
        const bf16* bl_p = Bs_l + b * BSZ;

#pragma unroll
        for (int kk = 0; kk < 2; kk++) {
            wmma::fragment<wmma::matrix_a, 16, 16, 16, bf16,
                           wmma::row_major> ah[2], al[2];
#pragma unroll
            for (int mi = 0; mi < 2; mi++) {
                wmma::load_matrix_sync(ah[mi], ah_p + (wm * 32 + mi * 16) * 40 + kk * 16, 40);
                wmma::load_matrix_sync(al[mi], al_p + (wm * 32 + mi * 16) * 40 + kk * 16, 40);
            }
            if (BT) {
                wmma::fragment<wmma::matrix_b, 16, 16, 16, bf16,
                               wmma::col_major> bh[4], bl[4];
#pragma unroll
                for (int ni = 0; ni < 4; ni++) {
                    wmma::load_matrix_sync(bh[ni], bh_p + (wn * 64 + ni * 16) * 40 + kk * 16, 40);
                    wmma::load_matrix_sync(bl[ni], bl_p + (wn * 64 + ni * 16) * 40 + kk * 16, 40);
                }
#pragma unroll
                for (int mi = 0; mi < 2; mi++)
#pragma unroll
                    for (int ni = 0; ni < 4; ni++) {
                        wmma::mma_sync(cf[mi][ni], ah[mi], bh[ni], cf[mi][ni]);
                        wmma::mma_sync(cf[mi][ni], al[mi], bh[ni], cf[mi][ni]);
                        wmma::mma_sync(cf[mi][ni], ah[mi], bl[ni], cf[mi][ni]);
                    }
            } else {
                wmma::fragment<wmma::matrix_b, 16, 16, 16, bf16,
                               wmma::row_major> bh[4], bl[4];
#pragma unroll
                for (int ni = 0; ni < 4; ni++) {
                    wmma::load_matrix_sync(bh[ni], bh_p + kk * 16 * 136 + wn * 64 + ni * 16, 136);
                    wmma::load_matrix_sync(bl[ni], bl_p + kk * 16 * 136 + wn * 64 + ni * 16, 136);
                }
#pragma unroll
                for (int mi = 0; mi < 2; mi++)
#pragma unroll
                    for (int ni = 0; ni < 4; ni++) {
                        wmma::mma_sync(cf[mi][ni], ah[mi], bh[ni], cf[mi][ni]);
                        wmma::mma_sync(cf[mi][ni], al[mi], bh[ni], cf[mi][ni]);
                        wmma::mma_sync(cf[mi][ni], ah[mi], bl[ni], cf[mi][ni]);
                    }
            }
        }
        __syncthreads();
    }

    if (HILO) {
        // stage accumulators to smem, convert to scaled bf16 hi/lo
        float* smemf = (float*)dyn;          // 64 x 132 pitch = 33 KB
        __syncthreads();
#pragma unroll
        for (int mi = 0; mi < 2; mi++)
#pragma unroll
            for (int ni = 0; ni < 4; ni++)
                wmma::store_matrix_sync(smemf + (wm * 32 + mi * 16) * 132
                                              + wn * 64 + ni * 16,
                                        cf[mi][ni], 132, wmma::mem_row_major);
        __syncthreads();
        const float sc = p.scale[z];
        bf16* __restrict__ Oh = p.Oh[z];
        bf16* __restrict__ Ol = p.Ol[z];
#pragma unroll
        for (int i = 0; i < 64; i++) {
            int idx = tid + i * 128;
            int r = idx >> 7, c = idx & 127;
            float val = smemf[r * 132 + c] * sc;
            bf16 h, l;
            split_bf16(val, h, l);
            size_t g = (size_t)(by * 64 + r) * N + bx * 128 + c;
            Oh[g] = h;
            Ol[g] = l;
        }
    } else {
        float* __restrict__ C = p.C[z];
#pragma unroll
        for (int mi = 0; mi < 2; mi++)
#pragma unroll
            for (int ni = 0; ni < 4; ni++) {
                float* Cp = C + (size_t)(by * 64 + wm * 32 + mi * 16) * N
                              + bx * 128 + wn * 64 + ni * 16;
                wmma::store_matrix_sync(Cp, cf[mi][ni], N, wmma::mem_row_major);
            }
    }
}

// ---------------- gelu + L2-norm, writing bf16 hi/lo ----------------------
__global__ void __launch_bounds__(256) gelu_l2norm_cvt(const float* __restrict__ in,
                                                       bf16* __restrict__ oh,
                                                       bf16* __restrict__ ol)
{
    const int row = blockIdx.x;
    const int tid = threadIdx.x;
    __shared__ float g[NTOK];
    __shared__ float ws[8];

    const float* rp = in + (size_t)row * NTOK;

    float ss = 0.f;
    for (int i = tid; i < NTOK; i += 256) {
        float v = rp[i];
        float gv = 0.5f * v * (1.f + erff(v * 0.70710678118654752f));
        g[i] = gv;
        ss += gv * gv;
    }
#pragma unroll
    for (int o = 16; o > 0; o >>= 1) ss += __shfl_xor_sync(0xffffffffu, ss, o);
    if ((tid & 31) == 0) ws[tid >> 5] = ss;
    __syncthreads();

    float tot = 0.f;
#pragma unroll
    for (int w = 0; w < 8; w++) tot += ws[w];

    const float sc = 32.f * rsqrtf(tot);
    for (int i = tid; i < NTOK; i += 256) {
        float v = g[i] * sc;
        bf16 h, l;
        split_bf16(v, h, l);
        oh[(size_t)row * NTOK + i] = h;
        ol[(size_t)row * NTOK + i] = l;
    }
}

// ---------------- tensor-core causal flash attention (wmma) ---------------
#define FPAD 72
#define SPAD 68

__global__ void __launch_bounds__(256) flash_tc(const bf16* __restrict__ qkvh,
                                                const bf16* __restrict__ qkvl,
                                                bf16* __restrict__ ctxh,
                                                bf16* __restrict__ ctxl)
{
    const size_t SZ = (size_t)SEQ * HID;
    const int tid  = threadIdx.x;
    const int wid  = tid >> 5;
    const int head = blockIdx.y;
    const int qt   = gridDim.x - 1 - blockIdx.x;
    const int hc   = head * HDIM;

    extern __shared__ char dynb[];
    bf16*  Qh  = (bf16*)dynb;
    bf16*  Ql  = Qh + 128 * FPAD;
    bf16*  KVs = Ql + 128 * FPAD;
    float* S   = (float*)(KVs + 2 * 4 * 64 * FPAD);
    float* O   = S + 128 * SPAD;
    bf16*  Ph  = (bf16*)(O + 128 * SPAD);
    bf16*  Pl  = Ph + 128 * FPAD;
    float* sm_m = (float*)(Pl + 128 * FPAD);
    float* sm_l = sm_m + 128;
    float* sm_c = sm_l + 128;

    for (int i = tid; i < 128 * SPAD; i += 256) O[i] = 0.f;
    if (tid < 128) { sm_m[tid] = -1e30f; sm_l[tid] = 0.f; }

    for (int i = tid; i < 1024; i += 256) {
        int r = i >> 3, c8 = (i & 7) * 8;
        size_t g = (size_t)(qt * 128 + r) * HID + hc + c8;
        cpa16(Qh + r * FPAD + c8, qkvh + g);
        cpa16(Ql + r * FPAD + c8, qkvl + g);
    }
    CPA_COMMIT();

    auto stageKV = [&](int step, int buf) {
        const int kb = step * 64;
        bf16* base = KVs + buf * (4 * 64 * FPAD);
        for (int i = tid; i < 512; i += 256) {
            int r = i >> 3, c8 = (i & 7) * 8;
            size_t g = (size_t)(kb + r) * HID + hc + c8;
            cpa16(base + 0 * 64 * FPAD + r * FPAD + c8, qkvh + SZ + g);
            cpa16(base + 1 * 64 * FPAD + r * FPAD + c8, qkvl + SZ + g);
            cpa16(base + 2 * 64 * FPAD + r * FPAD + c8, qkvh + 2 * SZ + g);
            cpa16(base + 3 * 64 * FPAD + r * FPAD + c8, qkvl + 2 * SZ + g);
        }
        CPA_COMMIT();
    };

    const int nsteps = 2 * qt + 2;
    stageKV(0, 0);
    CPA_WAIT(0);
    __syncthreads();

    const int wq = wid * 16;

    for (int step = 0; step < nsteps; step++) {
        const int buf = step & 1;
        const int kb  = step * 64;
        if (step + 1 < nsteps) { stageKV(step + 1, buf ^ 1); CPA_WAIT(1); }
        else                   { CPA_WAIT(0); }
        __syncthreads();

        const bf16* kh = KVs + buf * (4 * 64 * FPAD);
        const bf16* kl = kh + 64 * FPAD;
        const bf16* vh = kh + 2 * 64 * FPAD;
        const bf16* vl = kh + 3 * 64 * FPAD;

        {
            wmma::fragment<wmma::matrix_a, 16, 16, 16, bf16, wmma::row_major> ah[4], al[4];
#pragma unroll
            for (int ks = 0; ks < 4; ks++) {
                wmma::load_matrix_sync(ah[ks], Qh + wq * FPAD + ks * 16, FPAD);
                wmma::load_matrix_sync(al[ks], Ql + wq * FPAD + ks * 16, FPAD);
            }
#pragma unroll
            for (int nf = 0; nf < 4; nf++) {
                wmma::fragment<wmma::accumulator, 16, 16, 16, float> acc;
                wmma::fill_fragment(acc, 0.f);
#pragma unroll
                for (int ks = 0; ks < 4; ks++) {
                    wmma::fragment<wmma::matrix_b, 16, 16, 16, bf16, wmma::col_major> bh, bl;
                    wmma::load_matrix_sync(bh, kh + nf * 16 * FPAD + ks * 16, FPAD);
                    wmma::load_matrix_sync(bl, kl + nf * 16 * FPAD + ks * 16, FPAD);
                    wmma::mma_sync(acc, ah[ks], bh, acc);
                    wmma::mma_sync(acc, al[ks], bh, acc);
                    wmma::mma_sync(acc, ah[ks], bl, acc);
                }
                wmma::store_matrix_sync(S + wq * SPAD + nf * 16, acc, SPAD,
                                        wmma::mem_row_major);
            }
        }
        __syncthreads();

        if (tid < 128) {
            const int qrow = qt * 128 + tid;
            int jmax = qrow - kb + 1;
            if (jmax > 64) jmax = 64;
            unsigned* ph = (unsigned*)(Ph + tid * FPAD);
            unsigned* pl = (unsigned*)(Pl + tid * FPAD);
            if (jmax <= 0) {
                sm_c[tid] = 1.f;
#pragma unroll
                for (int j = 0; j < 32; j++) { ph[j] = 0u; pl[j] = 0u; }
            } else {
                const float* Srow = S + tid * SPAD;
                float m = sm_m[tid];
                float tmax = -1e30f;
                for (int j = 0; j < jmax; j++) tmax = fmaxf(tmax, Srow[j]);
                float mnew = fmaxf(m, tmax);
                float corr = __expf(m - mnew);
                float suml = 0.f;
                for (int j2 = 0; j2 < 32; j2++) {
                    int ja = 2 * j2, jb = 2 * j2 + 1;
                    float pa = (ja < jmax) ? __expf(Srow[ja] - mnew) : 0.f;
                    float pb = (jb < jmax) ? __expf(Srow[jb] - mnew) : 0.f;
                    suml += pa + pb;
                    bf16 ha, la, hb, lb;
                    split_bf16(pa, ha, la); split_bf16(pb, hb, lb);
                    ph[j2] = pb2(ha, hb);
                    pl[j2] = pb2(la, lb);
                }
                sm_l[tid] = sm_l[tid] * corr + suml;
                sm_m[tid] = mnew;
                sm_c[tid] = corr;
            }
        }
        __syncthreads();

        {
            wmma::fragment<wmma::matrix_a, 16, 16, 16, bf16, wmma::row_major> pah[4], pal[4];
#pragma unroll
            for (int ks = 0; ks < 4; ks++) {
                wmma::load_matrix_sync(pah[ks], Ph + wq * FPAD + ks * 16, FPAD);
                wmma::load_matrix_sync(pal[ks], Pl + wq * FPAD + ks * 16, FPAD);
            }
#pragma unroll
            for (int nf = 0; nf < 4; nf++) {
                wmma::fragment<wmma::accumulator, 16, 16, 16, float> acc;
                wmma::fill_fragment(acc, 0.f);
#pragma unroll
                for (int ks = 0; ks < 4; ks++) {
                    wmma::fragment<wmma::matrix_b, 16, 16, 16, bf16, wmma::row_major> bh, bl;
                    wmma::load_matrix_sync(bh, vh + ks * 16 * FPAD + nf * 16, FPAD);
                    wmma::load_matrix_sync(bl, vl + ks * 16 * FPAD + nf * 16, FPAD);
                    wmma::mma_sync(acc, pah[ks], bh, acc);
                    wmma::mma_sync(acc, pal[ks], bh, acc);
                    wmma::mma_sync(acc, pah[ks], bl, acc);
                }
                wmma::store_matrix_sync(S + wq * SPAD + nf * 16, acc, SPAD,
                                        wmma::mem_row_major);
            }
        }
        __syncthreads();

#pragma unroll
        for (int t = 0; t < 32; t++) {
            int idx = tid + t * 256;
            int r = idx >> 6, c = idx & 63;
            O[r * SPAD + c] = O[r * SPAD + c] * sm_c[r] + S[r * SPAD + c];
        }
        __syncthreads();
    }

#pragma unroll
    for (int t = 0; t < 32; t++) {
        int idx = tid + t * 256;
        int r = idx >> 6, c = idx & 63;
        float val = O[r * SPAD + c] / sm_l[r];
        bf16 h, l;
        split_bf16(val, h, l);
        size_t g = (size_t)(qt * 128 + r) * HID + hc + c;
        ctxh[g] = h;
        ctxl[g] = l;
    }
}

#define FLASH_SMEM (2*128*FPAD*2 + 2*4*64*FPAD*2 + 2*128*SPAD*4 + 2*128*FPAD*2 + 3*128*4 + 128)

// ---------------------------------------------------------------------------
extern "C" void kernel_launch(void* const* d_in, const int* in_sizes, int n_in,
                              void* d_out, int out_size)
{
    const float* x = (const float*)d_in[0];
    float* out = (float*)d_out;

    float* attnf;
    bf16 *attnh, *attnl, *xh, *xl, *ctxh, *ctxl, *wh, *wl, *qkvh, *qkvl;
    cudaGetSymbolAddress((void**)&attnf, g_attnf);
    cudaGetSymbolAddress((void**)&attnh, g_attnh);
    cudaGetSymbolAddress((void**)&attnl, g_attnl);
    cudaGetSymbolAddress((void**)&xh, g_xh);
    cudaGetSymbolAddress((void**)&xl, g_xl);
    cudaGetSymbolAddress((void**)&ctxh, g_ctxh);
    cudaGetSymbolAddress((void**)&ctxl, g_ctxl);
    cudaGetSymbolAddress((void**)&wh, g_wh);
    cudaGetSymbolAddress((void**)&wl, g_wl);
    cudaGetSymbolAddress((void**)&qkvh, g_qkvh);
    cudaGetSymbolAddress((void**)&qkvl, g_qkvl);

    cudaFuncSetAttribute(tgemm_bf16<true, false>,
                         cudaFuncAttributeMaxDynamicSharedMemorySize, GEMM_SMEM_BT);
    cudaFuncSetAttribute(tgemm_bf16<false, false>,
                         cudaFuncAttributeMaxDynamicSharedMemorySize, GEMM_SMEM_BN);
    cudaFuncSetAttribute(tgemm_bf16<false, true>,
                         cudaFuncAttributeMaxDynamicSharedMemorySize, GEMM_SMEM_BN);
    cudaFuncSetAttribute(flash_tc,
                         cudaFuncAttributeMaxDynamicSharedMemorySize, FLASH_SMEM);

    const size_t WSZ = (size_t)NTOK * HID;
    const size_t AS  = (size_t)SEQ * NTOK;
    const size_t SZ  = (size_t)SEQ * HID;

    // convert inputs to bf16 hi/lo
    cvt_hilo<<<SEQ * HID / 1024, 256>>>(x, xh, xl);
    W8 w8;
    for (int i = 0; i < 8; i++) w8.src[i] = (const float*)d_in[1 + i];
    cvt_hilo8<<<dim3(WSZ / 1024, 8), 256>>>(w8, wh, wl);

    dim3 gg3(HID / 128, SEQ / 64, 3);   // (8, 32, 3)
    dim3 gg1(HID / 128, SEQ / 64, 1);   // (8, 32)

    // ---- QKV pattention GEMM1 (x @ keys^T), batched over z ----
    GB p1 = {};
    for (int z = 0; z < 3; z++) {
        p1.Ah[z] = xh;  p1.Al[z] = xl;
        p1.Bh[z] = wh + (size_t)(z * 2) * WSZ;   // qk,kk,vk
        p1.Bl[z] = wl + (size_t)(z * 2) * WSZ;
        p1.C[z]  = attnf + z * AS;
    }
    tgemm_bf16<true, false><<<gg3, 128, GEMM_SMEM_BT>>>(p1, SEQ, NTOK, HID);

    gelu_l2norm_cvt<<<3 * SEQ, 256>>>(attnf, attnh, attnl);

    // ---- GEMM2 (w @ vals), fused epilogue -> scaled bf16 hi/lo q/k/v ----
    GB p2 = {};
    for (int z = 0; z < 3; z++) {
        p2.Ah[z] = attnh + z * AS;  p2.Al[z] = attnl + z * AS;
        p2.Bh[z] = wh + (size_t)(z * 2 + 1) * WSZ;   // qv,kv,vv
        p2.Bl[z] = wl + (size_t)(z * 2 + 1) * WSZ;
        p2.Oh[z] = qkvh + z * SZ;
        p2.Ol[z] = qkvl + z * SZ;
        p2.scale[z] = (z == 0) ? 0.125f : 1.f;
    }
    tgemm_bf16<false, true><<<gg3, 128, GEMM_SMEM_BN>>>(p2, SEQ, HID, NTOK);

    // ---- tensor-core causal attention -> ctx hi/lo ----
    flash_tc<<<dim3(SEQ / 128, NHEAD), 256, FLASH_SMEM>>>(qkvh, qkvl, ctxh, ctxl);

    // ---- output projection ----
    GB p3 = {};
    p3.Ah[0] = ctxh; p3.Al[0] = ctxl;
    p3.Bh[0] = wh + (size_t)6 * WSZ;  p3.Bl[0] = wl + (size_t)6 * WSZ;  // pk
    p3.C[0]  = attnf;
    tgemm_bf16<true, false><<<gg1, 128, GEMM_SMEM_BT>>>(p3, SEQ, NTOK, HID);

    gelu_l2norm_cvt<<<SEQ, 256>>>(attnf, attnh, attnl);

    GB p4 = {};
    p4.Ah[0] = attnh; p4.Al[0] = attnl;
    p4.Bh[0] = wh + (size_t)7 * WSZ;  p4.Bl[0] = wl + (size_t)7 * WSZ;  // pv
    p4.C[0]  = out;
    tgemm_bf16<false, false><<<gg1, 128, GEMM_SMEM_BN>>>(p4, SEQ, HID, NTOK);
}

// round 10
// speedup vs baseline: 2.5926x; 1.0068x over previous
#include <cuda_runtime.h>
#include <cuda_bf16.h>
#include <mma.h>
#include <math.h>
#include <cstdint>

using namespace nvcuda;

#define SEQ   2048
#define HID   1024
#define NTOK  1024
#define NHEAD 16
#define HDIM  64

typedef __nv_bfloat16 bf16;

#define PART (3 * SEQ * NTOK)   // stride between split-K partial slabs (floats)

// ---------------- scratch (device globals; no runtime allocation) ----------
__device__ float g_part[2 * 3 * SEQ * NTOK];   // split-K partials (48 MB)
__device__ bf16 g_attnh[3 * SEQ * NTOK];
__device__ bf16 g_attnl[3 * SEQ * NTOK];
__device__ bf16 g_xh[SEQ * HID], g_xl[SEQ * HID];
__device__ bf16 g_ctxh[SEQ * HID], g_ctxl[SEQ * HID];
__device__ bf16 g_wh[8][NTOK * HID];   // qk,qv,kk,kv,vk,vv,pk,pv
__device__ bf16 g_wl[8][NTOK * HID];
__device__ bf16 g_qkvh[3 * SEQ * HID]; // q(scaled),k,v hi
__device__ bf16 g_qkvl[3 * SEQ * HID];

// ---------------- small helpers -------------------------------------------
__device__ __forceinline__ unsigned short b2u(bf16 h) {
    return *reinterpret_cast<unsigned short*>(&h);
}
__device__ __forceinline__ unsigned pb2(bf16 a, bf16 b) {
    return (unsigned)b2u(a) | ((unsigned)b2u(b) << 16);
}
__device__ __forceinline__ void split_bf16(float x, bf16& h, bf16& l) {
    h = __float2bfloat16_rn(x);
    l = __float2bfloat16_rn(x - __bfloat162float(h));
}
__device__ __forceinline__ void cpa16(void* smem, const void* gmem) {
    unsigned s = (unsigned)__cvta_generic_to_shared(smem);
    asm volatile("cp.async.cg.shared.global [%0], [%1], 16;" :: "r"(s), "l"(gmem));
}
#define CPA_COMMIT() asm volatile("cp.async.commit_group;")
#define CPA_WAIT(n)  asm volatile("cp.async.wait_group %0;" :: "n"(n))

// ---------------- conversions ----------------------------------------------
__global__ void __launch_bounds__(256) cvt_hilo(const float* __restrict__ in,
                                                bf16* __restrict__ hi,
                                                bf16* __restrict__ lo)
{
    int i = (blockIdx.x * 256 + threadIdx.x) * 4;
    float4 v = *(const float4*)(in + i);
    bf16 h0, h1, h2, h3, l0, l1, l2, l3;
    split_bf16(v.x, h0, l0); split_bf16(v.y, h1, l1);
    split_bf16(v.z, h2, l2); split_bf16(v.w, h3, l3);
    uint2 H; H.x = pb2(h0, h1); H.y = pb2(h2, h3);
    uint2 L; L.x = pb2(l0, l1); L.y = pb2(l2, l3);
    *(uint2*)(hi + i) = H;
    *(uint2*)(lo + i) = L;
}

struct W8 { const float* src[8]; };

__global__ void __launch_bounds__(256) cvt_hilo8(W8 s,
                                                 bf16* __restrict__ hi,
                                                 bf16* __restrict__ lo)
{
    const size_t WSZ = (size_t)NTOK * HID;
    int z = blockIdx.y;
    int i = (blockIdx.x * 256 + threadIdx.x) * 4;
    float4 v = *(const float4*)(s.src[z] + i);
    bf16 h0, h1, h2, h3, l0, l1, l2, l3;
    split_bf16(v.x, h0, l0); split_bf16(v.y, h1, l1);
    split_bf16(v.z, h2, l2); split_bf16(v.w, h3, l3);
    uint2 H; H.x = pb2(h0, h1); H.y = pb2(h2, h3);
    uint2 L; L.x = pb2(l0, l1); L.y = pb2(l2, l3);
    *(uint2*)(hi + z * WSZ + i) = H;
    *(uint2*)(lo + z * WSZ + i) = L;
}

// split-K partial reduce + scale + bf16 hi/lo split (for q/k/v)
__global__ void __launch_bounds__(256) reduce_cvt_qkv(const float* __restrict__ part,
                                                      bf16* __restrict__ hi,
                                                      bf16* __restrict__ lo)
{
    const size_t SZ = (size_t)SEQ * HID;
    int z = blockIdx.y;
    const float sc = (z == 0) ? 0.125f : 1.f;
    size_t i = (size_t)(blockIdx.x * 256 + threadIdx.x) * 4 + z * SZ;
    float4 a = *(const float4*)(part + i);
    float4 b = *(const float4*)(part + PART + i);
    bf16 h0, h1, h2, h3, l0, l1, l2, l3;
    split_bf16((a.x + b.x) * sc, h0, l0); split_bf16((a.y + b.y) * sc, h1, l1);
    split_bf16((a.z + b.z) * sc, h2, l2); split_bf16((a.w + b.w) * sc, h3, l3);
    uint2 H; H.x = pb2(h0, h1); H.y = pb2(h2, h3);
    uint2 L; L.x = pb2(l0, l1); L.y = pb2(l2, l3);
    *(uint2*)(hi + i) = H;
    *(uint2*)(lo + i) = L;
}

// split-K partial reduce -> fp32 out (final projection)
__global__ void __launch_bounds__(256) reduce_out(const float* __restrict__ part,
                                                  float* __restrict__ out)
{
    size_t i = (size_t)(blockIdx.x * 256 + threadIdx.x) * 4;
    float4 a = *(const float4*)(part + i);
    float4 b = *(const float4*)(part + PART + i);
    *(float4*)(out + i) = make_float4(a.x + b.x, a.y + b.y, a.z + b.z, a.w + b.w);
}

// ---------------- tensor GEMM (bf16 hi/lo, 3 compensated terms, split-K=2) -
//  BT=true : B is [N,K] row-major (C = A*B^T)
//  BT=false: B is [K,N] row-major (C = A*B)
//  128x128 tile, BK=32, 256 threads (8 warps 4x2, warp tile 32x64).
//  blockIdx.z = zi*2 + ks; partial ks written to C[zi] + ks*PART.
struct GB {
    const bf16 *Ah[3], *Al[3], *Bh[3], *Bl[3];
    float* C[3];
};

#define ASZ 5120                       // 128*40 elems
#define BSZ_BT 5120                    // 128*40 elems
#define BSZ_NBT 4352                   // 32*136 elems
#define GEMM_SMEM_BT  ((4 * ASZ + 4 * BSZ_BT) * 2)    // 81920 bytes
#define GEMM_SMEM_BN  ((4 * ASZ + 4 * BSZ_NBT) * 2)   // 75776 bytes

template <bool BT>
__global__ void __launch_bounds__(256, 2) tgemm_bf16(GB p, int M, int N, int K)
{
    constexpr int BSZ = BT ? BSZ_BT : BSZ_NBT;

    extern __shared__ bf16 dyn[];
    bf16* As_h = dyn;                       // [2][ASZ]
    bf16* As_l = dyn + 2 * ASZ;
    bf16* Bs_h = dyn + 4 * ASZ;             // [2][BSZ]
    bf16* Bs_l = dyn + 4 * ASZ + 2 * BSZ;

    const int zi = blockIdx.z >> 1;
    const int ks = blockIdx.z & 1;
    const bf16* __restrict__ Ah = p.Ah[zi];
    const bf16* __restrict__ Al = p.Al[zi];
    const bf16* __restrict__ Bh = p.Bh[zi];
    const bf16* __restrict__ Bl = p.Bl[zi];
    float* __restrict__ C = p.C[zi] + (size_t)ks * PART;

    const int tid = threadIdx.x;
    const int bx = blockIdx.x;
    const int by = blockIdx.y;
    const int wid = tid >> 5;
    const int wm = wid & 3;
    const int wn = wid >> 2;
    const int kbase = ks * (K / 2);

    wmma::fragment<wmma::accumulator, 16, 16, 16, float> cf[2][4];
#pragma unroll
    for (int mi = 0; mi < 2; mi++)
#pragma unroll
        for (int ni = 0; ni < 4; ni++) wmma::fill_fragment(cf[mi][ni], 0.f);

    int arow[2], akq[2], bkr[2], bnq[2];
#pragma unroll
    for (int i = 0; i < 2; i++) {
        int c = tid + i * 256;
        arow[i] = c >> 2;  akq[i] = (c & 3) * 8;
        if (BT) { bkr[i] = c >> 2;  bnq[i] = (c & 3) * 8; }
        else    { bkr[i] = c >> 4;  bnq[i] = (c & 15) * 8; }
    }

    const int T = K / 64;   // half-K in BK=32 tiles

    auto stage = [&](int t, int b) {
        const int kt = kbase + t * 32;
#pragma unroll
        for (int i = 0; i < 2; i++) {
            cpa16(As_h + b * ASZ + arow[i] * 40 + akq[i],
                  Ah + (size_t)(by * 128 + arow[i]) * K + kt + akq[i]);
            cpa16(As_l + b * ASZ + arow[i] * 40 + akq[i],
                  Al + (size_t)(by * 128 + arow[i]) * K + kt + akq[i]);
            if (BT) {
                cpa16(Bs_h + b * BSZ + bkr[i] * 40 + bnq[i],
                      Bh + (size_t)(bx * 128 + bkr[i]) * K + kt + bnq[i]);
                cpa16(Bs_l + b * BSZ + bkr[i] * 40 + bnq[i],
                      Bl + (size_t)(bx * 128 + bkr[i]) * K + kt + bnq[i]);
            } else {
                cpa16(Bs_h + b * BSZ + bkr[i] * 136 + bnq[i],
                      Bh + (size_t)(kt + bkr[i]) * N + bx * 128 + bnq[i]);
                cpa16(Bs_l + b * BSZ + bkr[i] * 136 + bnq[i],
                      Bl + (size_t)(kt + bkr[i]) * N + bx * 128 + bnq[i]);
            }
        }
        CPA_COMMIT();
    };

    stage(0, 0);

    for (int t = 0; t < T; t++) {
        const int b = t & 1;
        if (t + 1 < T) { stage(t + 1, b ^ 1); CPA_WAIT(1); }
        else           { CPA_WAIT(0); }
        __syncthreads();

        const bf16* ah_p = As_h + b * ASZ;
        const bf16* al_p = As_l + b * ASZ;
        const bf16* bh_p = Bs_h + b * BSZ;
        const bf16* bl_p = Bs_l + b * BSZ;

#pragma unroll
        for (int kk = 0; kk < 2; kk++) {
            wmma::fragment<wmma::matrix_a, 16, 16, 16, bf16,
                           wmma::row_major> ah[2], al[2];
#pragma unroll
            for (int mi = 0; mi < 2; mi++) {
                wmma::load_matrix_sync(ah[mi], ah_p + (wm * 32 + mi * 16) * 40 + kk * 16, 40);
                wmma::load_matrix_sync(al[mi], al_p + (wm * 32 + mi * 16) * 40 + kk * 16, 40);
            }
            if (BT) {
                wmma::fragment<wmma::matrix_b, 16, 16, 16, bf16,
                               wmma::col_major> bh[4], bl[4];
#pragma unroll
                for (int ni = 0; ni < 4; ni++) {
                    wmma::load_matrix_sync(bh[ni], bh_p + (wn * 64 + ni * 16) * 40 + kk * 16, 40);
                    wmma::load_matrix_sync(bl[ni], bl_p + (wn * 64 + ni * 16) * 40 + kk * 16, 40);
                }
#pragma unroll
                for (int mi = 0; mi < 2; mi++)
#pragma unroll
                    for (int ni = 0; ni < 4; ni++) {
                        wmma::mma_sync(cf[mi][ni], ah[mi], bh[ni], cf[mi][ni]);
                        wmma::mma_sync(cf[mi][ni], al[mi], bh[ni], cf[mi][ni]);
                        wmma::mma_sync(cf[mi][ni], ah[mi], bl[ni], cf[mi][ni]);
                    }
            } else {
                wmma::fragment<wmma::matrix_b, 16, 16, 16, bf16,
                               wmma::row_major> bh[4], bl[4];
#pragma unroll
                for (int ni = 0; ni < 4; ni++) {
                    wmma::load_matrix_sync(bh[ni], bh_p + kk * 16 * 136 + wn * 64 + ni * 16, 136);
                    wmma::load_matrix_sync(bl[ni], bl_p + kk * 16 * 136 + wn * 64 + ni * 16, 136);
                }
#pragma unroll
                for (int mi = 0; mi < 2; mi++)
#pragma unroll
                    for (int ni = 0; ni < 4; ni++) {
                        wmma::mma_sync(cf[mi][ni], ah[mi], bh[ni], cf[mi][ni]);
                        wmma::mma_sync(cf[mi][ni], al[mi], bh[ni], cf[mi][ni]);
                        wmma::mma_sync(cf[mi][ni], ah[mi], bl[ni], cf[mi][ni]);
                    }
            }
        }
        __syncthreads();
    }

#pragma unroll
    for (int mi = 0; mi < 2; mi++)
#pragma unroll
        for (int ni = 0; ni < 4; ni++) {
            float* Cp = C + (size_t)(by * 128 + wm * 32 + mi * 16) * N
                          + bx * 128 + wn * 64 + ni * 16;
            wmma::store_matrix_sync(Cp, cf[mi][ni], N, wmma::mem_row_major);
        }
}

// ---------------- gelu + L2-norm over summed split-K partials -------------
__global__ void __launch_bounds__(256) gelu_l2norm_cvt(const float* __restrict__ part,
                                                       bf16* __restrict__ oh,
                                                       bf16* __restrict__ ol)
{
    const int row = blockIdx.x;
    const int tid = threadIdx.x;
    __shared__ float g[NTOK];
    __shared__ float ws[8];

    const float* p0 = part + (size_t)row * NTOK;
    const float* p1 = p0 + PART;

    float ss = 0.f;
    for (int i = tid; i < NTOK; i += 256) {
        float v = p0[i] + p1[i];
        float gv = 0.5f * v * (1.f + erff(v * 0.70710678118654752f));
        g[i] = gv;
        ss += gv * gv;
    }
#pragma unroll
    for (int o = 16; o > 0; o >>= 1) ss += __shfl_xor_sync(0xffffffffu, ss, o);
    if ((tid & 31) == 0) ws[tid >> 5] = ss;
    __syncthreads();

    float tot = 0.f;
#pragma unroll
    for (int w = 0; w < 8; w++) tot += ws[w];

    const float sc = 32.f * rsqrtf(tot);
    for (int i = tid; i < NTOK; i += 256) {
        float v = g[i] * sc;
        bf16 h, l;
        split_bf16(v, h, l);
        oh[(size_t)row * NTOK + i] = h;
        ol[(size_t)row * NTOK + i] = l;
    }
}

// ---------------- tensor-core causal flash attention (wmma) ---------------
#define FPAD 72
#define SPAD 68

__global__ void __launch_bounds__(256) flash_tc(const bf16* __restrict__ qkvh,
                                                const bf16* __restrict__ qkvl,
                                                bf16* __restrict__ ctxh,
                                                bf16* __restrict__ ctxl)
{
    const size_t SZ = (size_t)SEQ * HID;
    const int tid  = threadIdx.x;
    const int wid  = tid >> 5;
    const int head = blockIdx.y;
    const int qt   = gridDim.x - 1 - blockIdx.x;
    const int hc   = head * HDIM;

    extern __shared__ char dynb[];
    bf16*  Qh  = (bf16*)dynb;
    bf16*  Ql  = Qh + 128 * FPAD;
    bf16*  KVs = Ql + 128 * FPAD;
    float* S   = (float*)(KVs + 2 * 4 * 64 * FPAD);
    float* O   = S + 128 * SPAD;
    bf16*  Ph  = (bf16*)(O + 128 * SPAD);
    bf16*  Pl  = Ph + 128 * FPAD;
    float* sm_m = (float*)(Pl + 128 * FPAD);
    float* sm_l = sm_m + 128;
    float* sm_c = sm_l + 128;

    for (int i = tid; i < 128 * SPAD; i += 256) O[i] = 0.f;
    if (tid < 128) { sm_m[tid] = -1e30f; sm_l[tid] = 0.f; }

    for (int i = tid; i < 1024; i += 256) {
        int r = i >> 3, c8 = (i & 7) * 8;
        size_t g = (size_t)(qt * 128 + r) * HID + hc + c8;
        cpa16(Qh + r * FPAD + c8, qkvh + g);
        cpa16(Ql + r * FPAD + c8, qkvl + g);
    }
    CPA_COMMIT();

    auto stageKV = [&](int step, int buf) {
        const int kb = step * 64;
        bf16* base = KVs + buf * (4 * 64 * FPAD);
        for (int i = tid; i < 512; i += 256) {
            int r = i >> 3, c8 = (i & 7) * 8;
            size_t g = (size_t)(kb + r) * HID + hc + c8;
            cpa16(base + 0 * 64 * FPAD + r * FPAD + c8, qkvh + SZ + g);
            cpa16(base + 1 * 64 * FPAD + r * FPAD + c8, qkvl + SZ + g);
            cpa16(base + 2 * 64 * FPAD + r * FPAD + c8, qkvh + 2 * SZ + g);
            cpa16(base + 3 * 64 * FPAD + r * FPAD + c8, qkvl + 2 * SZ + g);
        }
        CPA_COMMIT();
    };

    const int nsteps = 2 * qt + 2;
    stageKV(0, 0);
    CPA_WAIT(0);
    __syncthreads();

    const int wq = wid * 16;

    for (int step = 0; step < nsteps; step++) {
        const int buf = step & 1;
        const int kb  = step * 64;
        if (step + 1 < nsteps) { stageKV(step + 1, buf ^ 1); CPA_WAIT(1); }
        else                   { CPA_WAIT(0); }
        __syncthreads();

        const bf16* kh = KVs + buf * (4 * 64 * FPAD);
        const bf16* kl = kh + 64 * FPAD;
        const bf16* vh = kh + 2 * 64 * FPAD;
        const bf16* vl = kh + 3 * 64 * FPAD;

        {
            wmma::fragment<wmma::matrix_a, 16, 16, 16, bf16, wmma::row_major> ah[4], al[4];
#pragma unroll
            for (int ks = 0; ks < 4; ks++) {
                wmma::load_matrix_sync(ah[ks], Qh + wq * FPAD + ks * 16, FPAD);
                wmma::load_matrix_sync(al[ks], Ql + wq * FPAD + ks * 16, FPAD);
            }
#pragma unroll
            for (int nf = 0; nf < 4; nf++) {
                wmma::fragment<wmma::accumulator, 16, 16, 16, float> acc;
                wmma::fill_fragment(acc, 0.f);
#pragma unroll
                for (int ks = 0; ks < 4; ks++) {
                    wmma::fragment<wmma::matrix_b, 16, 16, 16, bf16, wmma::col_major> bh, bl;
                    wmma::load_matrix_sync(bh, kh + nf * 16 * FPAD + ks * 16, FPAD);
                    wmma::load_matrix_sync(bl, kl + nf * 16 * FPAD + ks * 16, FPAD);
                    wmma::mma_sync(acc, ah[ks], bh, acc);
                    wmma::mma_sync(acc, al[ks], bh, acc);
                    wmma::mma_sync(acc, ah[ks], bl, acc);
                }
                wmma::store_matrix_sync(S + wq * SPAD + nf * 16, acc, SPAD,
                                        wmma::mem_row_major);
            }
        }
        __syncthreads();

        if (tid < 128) {
            const int qrow = qt * 128 + tid;
            int jmax = qrow - kb + 1;
            if (jmax > 64) jmax = 64;
            unsigned* ph = (unsigned*)(Ph + tid * FPAD);
            unsigned* pl = (unsigned*)(Pl + tid * FPAD);
            if (jmax <= 0) {
                sm_c[tid] = 1.f;
#pragma unroll
                for (int j = 0; j < 32; j++) { ph[j] = 0u; pl[j] = 0u; }
            } else {
                const float* Srow = S + tid * SPAD;
                float m = sm_m[tid];
                float tmax = -1e30f;
                for (int j = 0; j < jmax; j++) tmax = fmaxf(tmax, Srow[j]);
                float mnew = fmaxf(m, tmax);
                float corr = __expf(m - mnew);
                float suml = 0.f;
                for (int j2 = 0; j2 < 32; j2++) {
                    int ja = 2 * j2, jb = 2 * j2 + 1;
                    float pa = (ja < jmax) ? __expf(Srow[ja] - mnew) : 0.f;
                    float pb = (jb < jmax) ? __expf(Srow[jb] - mnew) : 0.f;
                    suml += pa + pb;
                    bf16 ha, la, hb, lb;
                    split_bf16(pa, ha, la); split_bf16(pb, hb, lb);
                    ph[j2] = pb2(ha, hb);
                    pl[j2] = pb2(la, lb);
                }
                sm_l[tid] = sm_l[tid] * corr + suml;
                sm_m[tid] = mnew;
                sm_c[tid] = corr;
            }
        }
        __syncthreads();

        {
            wmma::fragment<wmma::matrix_a, 16, 16, 16, bf16, wmma::row_major> pah[4], pal[4];
#pragma unroll
            for (int ks = 0; ks < 4; ks++) {
                wmma::load_matrix_sync(pah[ks], Ph + wq * FPAD + ks * 16, FPAD);
                wmma::load_matrix_sync(pal[ks], Pl + wq * FPAD + ks * 16, FPAD);
            }
#pragma unroll
            for (int nf = 0; nf < 4; nf++) {
                wmma::fragment<wmma::accumulator, 16, 16, 16, float> acc;
                wmma::fill_fragment(acc, 0.f);
#pragma unroll
                for (int ks = 0; ks < 4; ks++) {
                    wmma::fragment<wmma::matrix_b, 16, 16, 16, bf16, wmma::row_major> bh, bl;
                    wmma::load_matrix_sync(bh, vh + ks * 16 * FPAD + nf * 16, FPAD);
                    wmma::load_matrix_sync(bl, vl + ks * 16 * FPAD + nf * 16, FPAD);
                    wmma::mma_sync(acc, pah[ks], bh, acc);
                    wmma::mma_sync(acc, pal[ks], bh, acc);
                    wmma::mma_sync(acc, pah[ks], bl, acc);
                }
                wmma::store_matrix_sync(S + wq * SPAD + nf * 16, acc, SPAD,
                                        wmma::mem_row_major);
            }
        }
        __syncthreads();

#pragma unroll
        for (int t = 0; t < 32; t++) {
            int idx = tid + t * 256;
            int r = idx >> 6, c = idx & 63;
            O[r * SPAD + c] = O[r * SPAD + c] * sm_c[r] + S[r * SPAD + c];
        }
        __syncthreads();
    }

#pragma unroll
    for (int t = 0; t < 32; t++) {
        int idx = tid + t * 256;
        int r = idx >> 6, c = idx & 63;
        float val = O[r * SPAD + c] / sm_l[r];
        bf16 h, l;
        split_bf16(val, h, l);
        size_t g = (size_t)(qt * 128 + r) * HID + hc + c;
        ctxh[g] = h;
        ctxl[g] = l;
    }
}

#define FLASH_SMEM (2*128*FPAD*2 + 2*4*64*FPAD*2 + 2*128*SPAD*4 + 2*128*FPAD*2 + 3*128*4 + 128)

// ---------------------------------------------------------------------------
extern "C" void kernel_launch(void* const* d_in, const int* in_sizes, int n_in,
                              void* d_out, int out_size)
{
    const float* x = (const float*)d_in[0];
    float* out = (float*)d_out;

    float* part;
    bf16 *attnh, *attnl, *xh, *xl, *ctxh, *ctxl, *wh, *wl, *qkvh, *qkvl;
    cudaGetSymbolAddress((void**)&part, g_part);
    cudaGetSymbolAddress((void**)&attnh, g_attnh);
    cudaGetSymbolAddress((void**)&attnl, g_attnl);
    cudaGetSymbolAddress((void**)&xh, g_xh);
    cudaGetSymbolAddress((void**)&xl, g_xl);
    cudaGetSymbolAddress((void**)&ctxh, g_ctxh);
    cudaGetSymbolAddress((void**)&ctxl, g_ctxl);
    cudaGetSymbolAddress((void**)&wh, g_wh);
    cudaGetSymbolAddress((void**)&wl, g_wl);
    cudaGetSymbolAddress((void**)&qkvh, g_qkvh);
    cudaGetSymbolAddress((void**)&qkvl, g_qkvl);

    cudaFuncSetAttribute(tgemm_bf16<true>,
                         cudaFuncAttributeMaxDynamicSharedMemorySize, GEMM_SMEM_BT);
    cudaFuncSetAttribute(tgemm_bf16<false>,
                         cudaFuncAttributeMaxDynamicSharedMemorySize, GEMM_SMEM_BN);
    cudaFuncSetAttribute(flash_tc,
                         cudaFuncAttributeMaxDynamicSharedMemorySize, FLASH_SMEM);

    const size_t WSZ = (size_t)NTOK * HID;
    const size_t AS  = (size_t)SEQ * NTOK;
    const size_t SZ  = (size_t)SEQ * HID;

    // convert inputs to bf16 hi/lo
    cvt_hilo<<<SEQ * HID / 1024, 256>>>(x, xh, xl);
    W8 w8;
    for (int i = 0; i < 8; i++) w8.src[i] = (const float*)d_in[1 + i];
    cvt_hilo8<<<dim3(WSZ / 1024, 8), 256>>>(w8, wh, wl);

    dim3 gg3(HID / 128, SEQ / 128, 6);   // 3 z * splitK 2 = 768 CTAs
    dim3 gg1(HID / 128, SEQ / 128, 2);   // 1 z * splitK 2 = 256 CTAs

    // ---- QKV pattention GEMM1 (x @ keys^T), batched over z, split-K=2 ----
    GB p1 = {};
    for (int z = 0; z < 3; z++) {
        p1.Ah[z] = xh;  p1.Al[z] = xl;
        p1.Bh[z] = wh + (size_t)(z * 2) * WSZ;   // qk,kk,vk
        p1.Bl[z] = wl + (size_t)(z * 2) * WSZ;
        p1.C[z]  = part + z * AS;
    }
    tgemm_bf16<true><<<gg3, 256, GEMM_SMEM_BT>>>(p1, SEQ, NTOK, HID);

    gelu_l2norm_cvt<<<3 * SEQ, 256>>>(part, attnh, attnl);

    // ---- GEMM2 (w @ vals), split-K=2 -> partials -> reduce+scale+split ----
    GB p2 = {};
    for (int z = 0; z < 3; z++) {
        p2.Ah[z] = attnh + z * AS;  p2.Al[z] = attnl + z * AS;
        p2.Bh[z] = wh + (size_t)(z * 2 + 1) * WSZ;   // qv,kv,vv
        p2.Bl[z] = wl + (size_t)(z * 2 + 1) * WSZ;
        p2.C[z]  = part + z * SZ;
    }
    tgemm_bf16<false><<<gg3, 256, GEMM_SMEM_BN>>>(p2, SEQ, HID, NTOK);

    reduce_cvt_qkv<<<dim3(SEQ * HID / 1024, 3), 256>>>(part, qkvh, qkvl);

    // ---- tensor-core causal attention -> ctx hi/lo ----
    flash_tc<<<dim3(SEQ / 128, NHEAD), 256, FLASH_SMEM>>>(qkvh, qkvl, ctxh, ctxl);

    // ---- output projection, split-K=2 ----
    GB p3 = {};
    p3.Ah[0] = ctxh; p3.Al[0] = ctxl;
    p3.Bh[0] = wh + (size_t)6 * WSZ;  p3.Bl[0] = wl + (size_t)6 * WSZ;  // pk
    p3.C[0]  = part;
    tgemm_bf16<true><<<gg1, 256, GEMM_SMEM_BT>>>(p3, SEQ, NTOK, HID);

    gelu_l2norm_cvt<<<SEQ, 256>>>(part, attnh, attnl);

    GB p4 = {};
    p4.Ah[0] = attnh; p4.Al[0] = attnl;
    p4.Bh[0] = wh + (size_t)7 * WSZ;  p4.Bl[0] = wl + (size_t)7 * WSZ;  // pv
    p4.C[0]  = part;
    tgemm_bf16<false><<<gg1, 256, GEMM_SMEM_BN>>>(p4, SEQ, HID, NTOK);

    reduce_out<<<SEQ * HID / 1024, 256>>>(part, out);
}